// round 2
// baseline (speedup 1.0000x reference)
#include <cuda_runtime.h>
#include <cstdint>
#include <cstddef>

// Problem dims
#define Hd    512
#define Bn    64
#define OBSn  256
#define FUTn  256
#define Tn    512
#define G4    2048
#define BT    32768          // Bn*Tn
#define BF    16384          // Bn*FUTn
#define OUT1  16777216       // Bn*Tn*Hd

// ---------------- scratch (no allocation allowed; device globals) -------------
__device__ float d_XG[(size_t)BF * G4];        // x-gates, reused for attention scores
__device__ float d_LH[(size_t)BT * Hd];        // lstm_hidden (concat observed + lstm h)
__device__ float d_A1[(size_t)BT * Hd];
__device__ float d_A2[(size_t)BT * Hd];
__device__ float d_Qb[(size_t)BT * Hd];
__device__ float d_Kb[(size_t)BT * Hd];
__device__ float d_Vb[(size_t)BT * Hd];

// grid-barrier state for persistent LSTM
__device__ unsigned g_bar_cnt = 0;
__device__ volatile unsigned g_bar_gen = 0;

__device__ __forceinline__ float sigmoidf_(float x) { return 1.0f / (1.0f + expf(-x)); }

// ======================= TN GEMM: C = A[M,K] @ W[N,K]^T + b1 + b2 =============
__global__ __launch_bounds__(256) void gemm_tn(
    const float* __restrict__ A, const float* __restrict__ W,
    const float* __restrict__ b1, const float* __restrict__ b2,
    float* __restrict__ C, int M, int N, int K)
{
    __shared__ float As[8][132];
    __shared__ float Ws[8][132];
    const int m0 = blockIdx.y * 128, n0 = blockIdx.x * 128;
    const int t  = threadIdx.x;
    const int tx = t & 15, ty = t >> 4;
    const int lr = t >> 1, lk = (t & 1) * 4;

    float acc[8][8];
#pragma unroll
    for (int i = 0; i < 8; i++)
#pragma unroll
        for (int j = 0; j < 8; j++) acc[i][j] = 0.0f;

    const float* Ap = A + (size_t)(m0 + lr) * K + lk;
    const float* Wp = W + (size_t)(n0 + lr) * K + lk;

    for (int k0 = 0; k0 < K; k0 += 8) {
        float4 a4 = *(const float4*)(Ap + k0);
        float4 w4 = *(const float4*)(Wp + k0);
        As[lk + 0][lr] = a4.x; As[lk + 1][lr] = a4.y; As[lk + 2][lr] = a4.z; As[lk + 3][lr] = a4.w;
        Ws[lk + 0][lr] = w4.x; Ws[lk + 1][lr] = w4.y; Ws[lk + 2][lr] = w4.z; Ws[lk + 3][lr] = w4.w;
        __syncthreads();
#pragma unroll
        for (int k = 0; k < 8; k++) {
            float4 A0 = *(const float4*)&As[k][ty * 8];
            float4 A1v = *(const float4*)&As[k][ty * 8 + 4];
            float4 W0 = *(const float4*)&Ws[k][tx * 8];
            float4 W1v = *(const float4*)&Ws[k][tx * 8 + 4];
            float ar[8] = {A0.x, A0.y, A0.z, A0.w, A1v.x, A1v.y, A1v.z, A1v.w};
            float wr[8] = {W0.x, W0.y, W0.z, W0.w, W1v.x, W1v.y, W1v.z, W1v.w};
#pragma unroll
            for (int i = 0; i < 8; i++)
#pragma unroll
                for (int j = 0; j < 8; j++) acc[i][j] += ar[i] * wr[j];
        }
        __syncthreads();
    }

    float bb[8];
#pragma unroll
    for (int j = 0; j < 8; j++) {
        int n = n0 + tx * 8 + j;
        float v = b1 ? b1[n] : 0.0f;
        if (b2) v += b2[n];
        bb[j] = v;
    }
#pragma unroll
    for (int i = 0; i < 8; i++) {
        size_t row = (size_t)(m0 + ty * 8 + i) * N + n0 + tx * 8;
        float4 o0, o1;
        o0.x = acc[i][0] + bb[0]; o0.y = acc[i][1] + bb[1];
        o0.z = acc[i][2] + bb[2]; o0.w = acc[i][3] + bb[3];
        o1.x = acc[i][4] + bb[4]; o1.y = acc[i][5] + bb[5];
        o1.z = acc[i][6] + bb[6]; o1.w = acc[i][7] + bb[7];
        *(float4*)&C[row]     = o0;
        *(float4*)&C[row + 4] = o1;
    }
}

// ============== batched scores: S = scale * Q Kt^T with causal mask ===========
__global__ __launch_bounds__(256) void gemm_tn_scores(
    const float* __restrict__ Qm, const float* __restrict__ Km,
    float* __restrict__ C, float scale)
{
    __shared__ float As[8][132];
    __shared__ float Ws[8][132];
    const size_t bo = (size_t)blockIdx.z * 262144;
    const float* A = Qm + bo;
    const float* W = Km + bo;
    float* Cb = C + bo;
    const int m0 = blockIdx.y * 128, n0 = blockIdx.x * 128;
    const int t = threadIdx.x;
    const int tx = t & 15, ty = t >> 4;
    const int lr = t >> 1, lk = (t & 1) * 4;

    float acc[8][8];
#pragma unroll
    for (int i = 0; i < 8; i++)
#pragma unroll
        for (int j = 0; j < 8; j++) acc[i][j] = 0.0f;

    const float* Ap = A + (size_t)(m0 + lr) * 512 + lk;
    const float* Wp = W + (size_t)(n0 + lr) * 512 + lk;

    for (int k0 = 0; k0 < 512; k0 += 8) {
        float4 a4 = *(const float4*)(Ap + k0);
        float4 w4 = *(const float4*)(Wp + k0);
        As[lk + 0][lr] = a4.x; As[lk + 1][lr] = a4.y; As[lk + 2][lr] = a4.z; As[lk + 3][lr] = a4.w;
        Ws[lk + 0][lr] = w4.x; Ws[lk + 1][lr] = w4.y; Ws[lk + 2][lr] = w4.z; Ws[lk + 3][lr] = w4.w;
        __syncthreads();
#pragma unroll
        for (int k = 0; k < 8; k++) {
            float4 A0 = *(const float4*)&As[k][ty * 8];
            float4 A1v = *(const float4*)&As[k][ty * 8 + 4];
            float4 W0 = *(const float4*)&Ws[k][tx * 8];
            float4 W1v = *(const float4*)&Ws[k][tx * 8 + 4];
            float ar[8] = {A0.x, A0.y, A0.z, A0.w, A1v.x, A1v.y, A1v.z, A1v.w};
            float wr[8] = {W0.x, W0.y, W0.z, W0.w, W1v.x, W1v.y, W1v.z, W1v.w};
#pragma unroll
            for (int i = 0; i < 8; i++)
#pragma unroll
                for (int j = 0; j < 8; j++) acc[i][j] += ar[i] * wr[j];
        }
        __syncthreads();
    }
#pragma unroll
    for (int i = 0; i < 8; i++) {
        int q = m0 + ty * 8 + i;
#pragma unroll
        for (int j = 0; j < 8; j++) {
            int kk = n0 + tx * 8 + j;
            float v = acc[i][j] * scale;
            if (kk > q) v = -1e30f;
            Cb[(size_t)q * 512 + kk] = v;
        }
    }
}

// ==================== batched NN GEMM: O = attn[512,512] @ V[512,512] =========
__global__ __launch_bounds__(256) void gemm_nn_b(
    const float* __restrict__ Am, const float* __restrict__ Bm, float* __restrict__ C)
{
    __shared__ float As[8][132];
    __shared__ float Bs[8][128];
    const size_t bo = (size_t)blockIdx.z * 262144;
    const float* A = Am + bo;
    const float* B = Bm + bo;
    float* Cb = C + bo;
    const int m0 = blockIdx.y * 128, n0 = blockIdx.x * 128;
    const int t = threadIdx.x;
    const int tx = t & 15, ty = t >> 4;
    const int lr = t >> 1, lk = (t & 1) * 4;
    const int kr = t >> 5, nq = t & 31;

    float acc[8][8];
#pragma unroll
    for (int i = 0; i < 8; i++)
#pragma unroll
        for (int j = 0; j < 8; j++) acc[i][j] = 0.0f;

    const float* Ap = A + (size_t)(m0 + lr) * 512 + lk;

    for (int k0 = 0; k0 < 512; k0 += 8) {
        float4 a4 = *(const float4*)(Ap + k0);
        float4 b4 = *(const float4*)(B + (size_t)(k0 + kr) * 512 + n0 + nq * 4);
        As[lk + 0][lr] = a4.x; As[lk + 1][lr] = a4.y; As[lk + 2][lr] = a4.z; As[lk + 3][lr] = a4.w;
        *(float4*)&Bs[kr][nq * 4] = b4;
        __syncthreads();
#pragma unroll
        for (int k = 0; k < 8; k++) {
            float4 A0 = *(const float4*)&As[k][ty * 8];
            float4 A1v = *(const float4*)&As[k][ty * 8 + 4];
            float4 W0 = *(const float4*)&Bs[k][tx * 8];
            float4 W1v = *(const float4*)&Bs[k][tx * 8 + 4];
            float ar[8] = {A0.x, A0.y, A0.z, A0.w, A1v.x, A1v.y, A1v.z, A1v.w};
            float wr[8] = {W0.x, W0.y, W0.z, W0.w, W1v.x, W1v.y, W1v.z, W1v.w};
#pragma unroll
            for (int i = 0; i < 8; i++)
#pragma unroll
                for (int j = 0; j < 8; j++) acc[i][j] += ar[i] * wr[j];
        }
        __syncthreads();
    }
#pragma unroll
    for (int i = 0; i < 8; i++) {
        size_t row = (size_t)(m0 + ty * 8 + i) * 512 + n0 + tx * 8;
        float4 o0, o1;
        o0.x = acc[i][0]; o0.y = acc[i][1]; o0.z = acc[i][2]; o0.w = acc[i][3];
        o1.x = acc[i][4]; o1.y = acc[i][5]; o1.z = acc[i][6]; o1.w = acc[i][7];
        *(float4*)&Cb[row]     = o0;
        *(float4*)&Cb[row + 4] = o1;
    }
}

// ======================= copy observed rows into lstm_hidden ==================
__global__ void copy_obs_k(const float* __restrict__ obs, float* __restrict__ LH)
{
    size_t i = (size_t)blockIdx.x * blockDim.x + threadIdx.x;
    if (i < (size_t)Bn * OBSn * Hd) {
        size_t b = i >> 17;
        size_t rem = i & 131071;
        LH[b * 262144 + rem] = obs[i];
    }
}

// ================= persistent LSTM: 128 blocks, all 256 steps =================
// Block b owns units [4b, 4b+4): gate rows {g*512 + 4b + j}. Weights (16 rows x
// 512) live in SMEM for all steps; cell state lives in a register per thread.
// One atomic grid barrier per step. Row stride padded to 520 floats (bank-safe).
#define HROW 520
__global__ __launch_bounds__(256, 1) void lstm_persist(
    const float* __restrict__ obs, const float* __restrict__ XG,
    const float* __restrict__ Whh, float* __restrict__ LH)
{
    extern __shared__ float sh[];
    float* Hs  = sh;                 // 64 x HROW
    float* Wsm = sh + 64 * HROW;     // 16 x HROW
    __shared__ float gsm[16 * 65];

    const int t = threadIdx.x;
    const int ublk = blockIdx.x * 4;
    const unsigned nb = gridDim.x;

    // ---- preload weights (once) ----
    {
        int rr = t >> 4, seg = t & 15;       // rr 0..15, seg 0..15
        int g = rr >> 2, j = rr & 3;
        const float4* src = (const float4*)(Whh + (size_t)(g * 512 + ublk + j) * 512) + seg * 8;
        float4* dst = (float4*)(Wsm + rr * HROW) + seg * 8;
#pragma unroll
        for (int i = 0; i < 8; i++) dst[i] = src[i];
    }

    // ---- pointwise role: thread t -> (batch pm, unit offset pj); c in register
    const int pm = t >> 2, pj = t & 3;
    float c_reg = obs[(size_t)pm * 131072 + 255 * 512 + ublk + pj];

    // ---- compute role: 2m x 2r microtile
    const int tx = t & 7, tm = t >> 3;
    const int r0 = 2 * tx, r1 = r0 + 1;
    const int m0 = 2 * tm, m1 = m0 + 1;

    for (int s = 0; s < 256; s++) {
        // load h_prev [64 x 512] into SMEM (bypass L1: written by other SMs)
        {
            const float* hsrc; size_t hstr;
            if (s == 0) { hsrc = obs + 255 * 512; hstr = 131072; }
            else        { hsrc = LH + (size_t)(255 + s) * 512; hstr = 262144; }
            int lm = t >> 2, q = t & 3;
            const float4* src = (const float4*)(hsrc + (size_t)lm * hstr) + q * 32;
            float4* dst = (float4*)(Hs + lm * HROW) + q * 32;
#pragma unroll 8
            for (int i = 0; i < 32; i++) dst[i] = __ldcg(src + i);
        }
        __syncthreads();

        // gates GEMV: 4 dots of length 512
        const float4* H4 = (const float4*)Hs;
        const float4* W4 = (const float4*)Wsm;
        const float4* h0p = H4 + m0 * (HROW / 4);
        const float4* h1p = H4 + m1 * (HROW / 4);
        const float4* w0p = W4 + r0 * (HROW / 4);
        const float4* w1p = W4 + r1 * (HROW / 4);
        float acc00 = 0.f, acc01 = 0.f, acc10 = 0.f, acc11 = 0.f;
#pragma unroll 4
        for (int kk = 0; kk < 128; kk++) {
            float4 a0 = h0p[kk], a1 = h1p[kk], b0 = w0p[kk], b1 = w1p[kk];
            acc00 += a0.x * b0.x + a0.y * b0.y + a0.z * b0.z + a0.w * b0.w;
            acc01 += a0.x * b1.x + a0.y * b1.y + a0.z * b1.z + a0.w * b1.w;
            acc10 += a1.x * b0.x + a1.y * b0.y + a1.z * b0.z + a1.w * b0.w;
            acc11 += a1.x * b1.x + a1.y * b1.y + a1.z * b1.z + a1.w * b1.w;
        }
        gsm[r0 * 65 + m0] = acc00;
        gsm[r1 * 65 + m0] = acc01;
        gsm[r0 * 65 + m1] = acc10;
        gsm[r1 * 65 + m1] = acc11;
        __syncthreads();

        // pointwise gate math + h store
        {
            const float* xrow = XG + (size_t)(pm * 256 + s) * 2048 + ublk + pj;
            float gi = gsm[(0 + pj) * 65 + pm]  + xrow[0];
            float gf = gsm[(4 + pj) * 65 + pm]  + xrow[512];
            float gg = gsm[(8 + pj) * 65 + pm]  + xrow[1024];
            float go = gsm[(12 + pj) * 65 + pm] + xrow[1536];
            c_reg = sigmoidf_(gf) * c_reg + sigmoidf_(gi) * tanhf(gg);
            float hv = sigmoidf_(go) * tanhf(c_reg);
            LH[(size_t)pm * 262144 + (size_t)(256 + s) * 512 + ublk + pj] = hv;
        }

        // grid barrier
        __threadfence();
        __syncthreads();
        if (t == 0) {
            unsigned snap = g_bar_gen;
            unsigned old = atomicAdd(&g_bar_cnt, 1u);
            if (old == nb - 1u) {
                g_bar_cnt = 0;
                __threadfence();
                g_bar_gen = snap + 1u;
            } else {
                while (g_bar_gen == snap) __nanosleep(40);
            }
            __threadfence();
        }
        __syncthreads();
    }
}

// ====================== fused GLU + LayerNorm (one block/row) =================
__global__ __launch_bounds__(256) void gluln_k(
    const float* __restrict__ a1, const float* __restrict__ a2,
    const float* __restrict__ y1, const float* __restrict__ y2,
    const float* __restrict__ gamma, const float* __restrict__ beta,
    float* __restrict__ outp, int splitY)
{
    __shared__ float red[8];
    const int r = blockIdx.x;
    const int t = threadIdx.x;
    const float* yp;
    if (splitY) {
        int b = r >> 9, tt = r & 511;
        yp = (tt < 256) ? (y1 + ((size_t)(b * 256 + tt)) * 512)
                        : (y2 + ((size_t)(b * 256 + tt - 256)) * 512);
    } else {
        yp = y1 + (size_t)r * 512;
    }
    const float* p1 = a1 + (size_t)r * 512;
    const float* p2 = a2 + (size_t)r * 512;
    float z0 = sigmoidf_(p1[t])       * p2[t]       + yp[t];
    float z1 = sigmoidf_(p1[t + 256]) * p2[t + 256] + yp[t + 256];

    float s = z0 + z1;
#pragma unroll
    for (int o = 16; o > 0; o >>= 1) s += __shfl_xor_sync(0xffffffffu, s, o);
    if ((t & 31) == 0) red[t >> 5] = s;
    __syncthreads();
    if (t < 32) {
        float a = (t < 8) ? red[t] : 0.0f;
#pragma unroll
        for (int o = 4; o > 0; o >>= 1) a += __shfl_xor_sync(0xffffffffu, a, o);
        if (t == 0) red[0] = a;
    }
    __syncthreads();
    float mu = red[0] * (1.0f / 512.0f);
    float d0 = z0 - mu, d1 = z1 - mu;
    float s2 = d0 * d0 + d1 * d1;
    __syncthreads();
#pragma unroll
    for (int o = 16; o > 0; o >>= 1) s2 += __shfl_xor_sync(0xffffffffu, s2, o);
    if ((t & 31) == 0) red[t >> 5] = s2;
    __syncthreads();
    if (t < 32) {
        float a = (t < 8) ? red[t] : 0.0f;
#pragma unroll
        for (int o = 4; o > 0; o >>= 1) a += __shfl_xor_sync(0xffffffffu, a, o);
        if (t == 0) red[0] = a;
    }
    __syncthreads();
    float inv = rsqrtf(red[0] * (1.0f / 512.0f) + 1e-5f);
    outp[(size_t)r * 512 + t]       = gamma[t]       * d0 * inv + beta[t];
    outp[(size_t)r * 512 + t + 256] = gamma[t + 256] * d1 * inv + beta[t + 256];
}

// ========================= row softmax over 512 cols ==========================
__global__ __launch_bounds__(256) void softmax_k(
    const float* __restrict__ S, float* __restrict__ A)
{
    __shared__ float red[8];
    const int r = blockIdx.x;
    const int t = threadIdx.x;
    const float* p = S + (size_t)r * 512;
    float v0 = p[t], v1 = p[t + 256];
    float m = fmaxf(v0, v1);
#pragma unroll
    for (int o = 16; o > 0; o >>= 1) m = fmaxf(m, __shfl_xor_sync(0xffffffffu, m, o));
    if ((t & 31) == 0) red[t >> 5] = m;
    __syncthreads();
    if (t < 32) {
        float a = (t < 8) ? red[t] : -3.4e38f;
#pragma unroll
        for (int o = 4; o > 0; o >>= 1) a = fmaxf(a, __shfl_xor_sync(0xffffffffu, a, o));
        if (t == 0) red[0] = a;
    }
    __syncthreads();
    float mx = red[0];
    float e0 = expf(v0 - mx), e1 = expf(v1 - mx);
    float s = e0 + e1;
    __syncthreads();
#pragma unroll
    for (int o = 16; o > 0; o >>= 1) s += __shfl_xor_sync(0xffffffffu, s, o);
    if ((t & 31) == 0) red[t >> 5] = s;
    __syncthreads();
    if (t < 32) {
        float a = (t < 8) ? red[t] : 0.0f;
#pragma unroll
        for (int o = 4; o > 0; o >>= 1) a += __shfl_xor_sync(0xffffffffu, a, o);
        if (t == 0) red[0] = a;
    }
    __syncthreads();
    float inv = 1.0f / red[0];
    A[(size_t)r * 512 + t]       = e0 * inv;
    A[(size_t)r * 512 + t + 256] = e1 * inv;
}

// ================================= host =======================================
extern "C" void kernel_launch(void* const* d_in, const int* in_sizes, int n_in,
                              void* d_out, int out_size)
{
    const float* obs   = (const float*)d_in[0];
    const float* fut   = (const float*)d_in[1];
    const float* W_ih  = (const float*)d_in[2];
    const float* W_hh  = (const float*)d_in[3];
    const float* b_ih  = (const float*)d_in[4];
    const float* b_hh  = (const float*)d_in[5];
    const float* g1W1  = (const float*)d_in[6];
    const float* g1b1  = (const float*)d_in[7];
    const float* g1W2  = (const float*)d_in[8];
    const float* g1b2  = (const float*)d_in[9];
    const float* g1g   = (const float*)d_in[10];
    const float* g1b   = (const float*)d_in[11];
    const float* Wq    = (const float*)d_in[12];
    const float* bq    = (const float*)d_in[13];
    const float* Wk    = (const float*)d_in[14];
    const float* bk    = (const float*)d_in[15];
    const float* Wv    = (const float*)d_in[16];
    const float* bv    = (const float*)d_in[17];
    const float* Wo    = (const float*)d_in[18];
    const float* bo    = (const float*)d_in[19];
    const float* g2W1  = (const float*)d_in[20];
    const float* g2b1  = (const float*)d_in[21];
    const float* g2W2  = (const float*)d_in[22];
    const float* g2b2  = (const float*)d_in[23];
    const float* g2g   = (const float*)d_in[24];
    const float* g2b   = (const float*)d_in[25];

    float* out       = (float*)d_out;
    float* glu_delta = out;
    float* glu_phi   = out + (size_t)OUT1;
    float* attn      = out + (size_t)2 * OUT1;

    float *XG, *LH, *A1, *A2, *Qb, *Kb, *Vb;
    cudaGetSymbolAddress((void**)&XG, d_XG);
    cudaGetSymbolAddress((void**)&LH, d_LH);
    cudaGetSymbolAddress((void**)&A1, d_A1);
    cudaGetSymbolAddress((void**)&A2, d_A2);
    cudaGetSymbolAddress((void**)&Qb, d_Qb);
    cudaGetSymbolAddress((void**)&Kb, d_Kb);
    cudaGetSymbolAddress((void**)&Vb, d_Vb);

    // 1. X_gates = fut @ W_ih^T + (b_ih + b_hh)
    gemm_tn<<<dim3(G4 / 128, BF / 128), 256>>>(fut, W_ih, b_ih, b_hh, XG, BF, G4, Hd);

    // 2. lstm_hidden[:, :256, :] = vsn_observed
    copy_obs_k<<<(Bn * OBSn * Hd + 255) / 256, 256>>>(obs, LH);

    // 3. persistent LSTM over all 256 steps
    {
        const int smem = (64 + 16) * HROW * 4;   // 166400 bytes
        cudaFuncSetAttribute(lstm_persist, cudaFuncAttributeMaxDynamicSharedMemorySize, smem);
        lstm_persist<<<128, 256, smem>>>(obs, XG, W_hh, LH);
    }

    // 4. GLU-LN #1 -> glu_phi
    gemm_tn<<<dim3(4, 256), 256>>>(LH, g1W1, g1b1, nullptr, A1, BT, Hd, Hd);
    gemm_tn<<<dim3(4, 256), 256>>>(LH, g1W2, g1b2, nullptr, A2, BT, Hd, Hd);
    gluln_k<<<BT, 256>>>(A1, A2, obs, fut, g1g, g1b, glu_phi, 1);

    // 5. QKV
    gemm_tn<<<dim3(4, 256), 256>>>(glu_phi, Wq, bq, nullptr, Qb, BT, Hd, Hd);
    gemm_tn<<<dim3(4, 256), 256>>>(glu_phi, Wk, bk, nullptr, Kb, BT, Hd, Hd);
    gemm_tn<<<dim3(4, 256), 256>>>(glu_phi, Wv, bv, nullptr, Vb, BT, Hd, Hd);

    // 6. scores (reuse XG) + softmax -> attn
    gemm_tn_scores<<<dim3(4, 4, 64), 256>>>(Qb, Kb, XG, 0.04419417382415922f);
    softmax_k<<<BT, 256>>>(XG, attn);

    // 7. attn @ V -> reuse Qb; projection -> reuse Kb
    gemm_nn_b<<<dim3(4, 4, 64), 256>>>(attn, Vb, Qb);
    gemm_tn<<<dim3(4, 256), 256>>>(Qb, Wo, bo, nullptr, Kb, BT, Hd, Hd);

    // 8. GLU-LN #2 -> glu_delta
    gemm_tn<<<dim3(4, 256), 256>>>(Kb, g2W1, g2b1, nullptr, A1, BT, Hd, Hd);
    gemm_tn<<<dim3(4, 256), 256>>>(Kb, g2W2, g2b2, nullptr, A2, BT, Hd, Hd);
    gluln_k<<<BT, 256>>>(A1, A2, glu_phi, nullptr, g2g, g2b, glu_delta, 0);
}

// round 3
// speedup vs baseline: 1.2038x; 1.2038x over previous
#include <cuda_runtime.h>
#include <cstdint>
#include <cstddef>

// Problem dims
#define Hd    512
#define Bn    64
#define OBSn  256
#define FUTn  256
#define Tn    512
#define G4    2048
#define BT    32768          // Bn*Tn
#define BF    16384          // Bn*FUTn
#define OUT1  16777216       // Bn*Tn*Hd

// ---------------- scratch (no allocation allowed; device globals) -------------
__device__ float d_XG[(size_t)BF * G4];        // x-gates, reused for attention scores
__device__ float d_LH[(size_t)BT * Hd];        // lstm_hidden (concat observed + lstm h)
__device__ float d_A1[(size_t)BT * Hd];
__device__ float d_A2[(size_t)BT * Hd];
__device__ float d_Qb[(size_t)BT * Hd];
__device__ float d_Kb[(size_t)BT * Hd];
__device__ float d_Vb[(size_t)BT * Hd];

// grid-barrier state for persistent LSTM (monotonic generation: replay-safe)
__device__ unsigned g_bar_cnt = 0;
__device__ volatile unsigned g_bar_gen = 0;

__device__ __forceinline__ float sigmoidf_(float x) { return 1.0f / (1.0f + expf(-x)); }

// ======================= TN GEMM: C = A[M,K] @ W[N,K]^T + b1 + b2 =============
__global__ __launch_bounds__(256) void gemm_tn(
    const float* __restrict__ A, const float* __restrict__ W,
    const float* __restrict__ b1, const float* __restrict__ b2,
    float* __restrict__ C, int M, int N, int K)
{
    __shared__ float As[8][132];
    __shared__ float Ws[8][132];
    const int m0 = blockIdx.y * 128, n0 = blockIdx.x * 128;
    const int t  = threadIdx.x;
    const int tx = t & 15, ty = t >> 4;
    const int lr = t >> 1, lk = (t & 1) * 4;

    float acc[8][8];
#pragma unroll
    for (int i = 0; i < 8; i++)
#pragma unroll
        for (int j = 0; j < 8; j++) acc[i][j] = 0.0f;

    const float* Ap = A + (size_t)(m0 + lr) * K + lk;
    const float* Wp = W + (size_t)(n0 + lr) * K + lk;

    for (int k0 = 0; k0 < K; k0 += 8) {
        float4 a4 = *(const float4*)(Ap + k0);
        float4 w4 = *(const float4*)(Wp + k0);
        As[lk + 0][lr] = a4.x; As[lk + 1][lr] = a4.y; As[lk + 2][lr] = a4.z; As[lk + 3][lr] = a4.w;
        Ws[lk + 0][lr] = w4.x; Ws[lk + 1][lr] = w4.y; Ws[lk + 2][lr] = w4.z; Ws[lk + 3][lr] = w4.w;
        __syncthreads();
#pragma unroll
        for (int k = 0; k < 8; k++) {
            float4 A0 = *(const float4*)&As[k][ty * 8];
            float4 A1v = *(const float4*)&As[k][ty * 8 + 4];
            float4 W0 = *(const float4*)&Ws[k][tx * 8];
            float4 W1v = *(const float4*)&Ws[k][tx * 8 + 4];
            float ar[8] = {A0.x, A0.y, A0.z, A0.w, A1v.x, A1v.y, A1v.z, A1v.w};
            float wr[8] = {W0.x, W0.y, W0.z, W0.w, W1v.x, W1v.y, W1v.z, W1v.w};
#pragma unroll
            for (int i = 0; i < 8; i++)
#pragma unroll
                for (int j = 0; j < 8; j++) acc[i][j] += ar[i] * wr[j];
        }
        __syncthreads();
    }

    float bb[8];
#pragma unroll
    for (int j = 0; j < 8; j++) {
        int n = n0 + tx * 8 + j;
        float v = b1 ? b1[n] : 0.0f;
        if (b2) v += b2[n];
        bb[j] = v;
    }
#pragma unroll
    for (int i = 0; i < 8; i++) {
        size_t row = (size_t)(m0 + ty * 8 + i) * N + n0 + tx * 8;
        float4 o0, o1;
        o0.x = acc[i][0] + bb[0]; o0.y = acc[i][1] + bb[1];
        o0.z = acc[i][2] + bb[2]; o0.w = acc[i][3] + bb[3];
        o1.x = acc[i][4] + bb[4]; o1.y = acc[i][5] + bb[5];
        o1.z = acc[i][6] + bb[6]; o1.w = acc[i][7] + bb[7];
        *(float4*)&C[row]     = o0;
        *(float4*)&C[row + 4] = o1;
    }
}

// ============== batched scores: S = scale * Q Kt^T with causal mask ===========
__global__ __launch_bounds__(256) void gemm_tn_scores(
    const float* __restrict__ Qm, const float* __restrict__ Km,
    float* __restrict__ C, float scale)
{
    __shared__ float As[8][132];
    __shared__ float Ws[8][132];
    const size_t bo = (size_t)blockIdx.z * 262144;
    const float* A = Qm + bo;
    const float* W = Km + bo;
    float* Cb = C + bo;
    const int m0 = blockIdx.y * 128, n0 = blockIdx.x * 128;
    const int t = threadIdx.x;
    const int tx = t & 15, ty = t >> 4;
    const int lr = t >> 1, lk = (t & 1) * 4;

    float acc[8][8];
#pragma unroll
    for (int i = 0; i < 8; i++)
#pragma unroll
        for (int j = 0; j < 8; j++) acc[i][j] = 0.0f;

    const float* Ap = A + (size_t)(m0 + lr) * 512 + lk;
    const float* Wp = W + (size_t)(n0 + lr) * 512 + lk;

    for (int k0 = 0; k0 < 512; k0 += 8) {
        float4 a4 = *(const float4*)(Ap + k0);
        float4 w4 = *(const float4*)(Wp + k0);
        As[lk + 0][lr] = a4.x; As[lk + 1][lr] = a4.y; As[lk + 2][lr] = a4.z; As[lk + 3][lr] = a4.w;
        Ws[lk + 0][lr] = w4.x; Ws[lk + 1][lr] = w4.y; Ws[lk + 2][lr] = w4.z; Ws[lk + 3][lr] = w4.w;
        __syncthreads();
#pragma unroll
        for (int k = 0; k < 8; k++) {
            float4 A0 = *(const float4*)&As[k][ty * 8];
            float4 A1v = *(const float4*)&As[k][ty * 8 + 4];
            float4 W0 = *(const float4*)&Ws[k][tx * 8];
            float4 W1v = *(const float4*)&Ws[k][tx * 8 + 4];
            float ar[8] = {A0.x, A0.y, A0.z, A0.w, A1v.x, A1v.y, A1v.z, A1v.w};
            float wr[8] = {W0.x, W0.y, W0.z, W0.w, W1v.x, W1v.y, W1v.z, W1v.w};
#pragma unroll
            for (int i = 0; i < 8; i++)
#pragma unroll
                for (int j = 0; j < 8; j++) acc[i][j] += ar[i] * wr[j];
        }
        __syncthreads();
    }
#pragma unroll
    for (int i = 0; i < 8; i++) {
        int q = m0 + ty * 8 + i;
#pragma unroll
        for (int j = 0; j < 8; j++) {
            int kk = n0 + tx * 8 + j;
            float v = acc[i][j] * scale;
            if (kk > q) v = -1e30f;
            Cb[(size_t)q * 512 + kk] = v;
        }
    }
}

// ==================== batched NN GEMM: O = attn[512,512] @ V[512,512] =========
__global__ __launch_bounds__(256) void gemm_nn_b(
    const float* __restrict__ Am, const float* __restrict__ Bm, float* __restrict__ C)
{
    __shared__ float As[8][132];
    __shared__ float Bs[8][128];
    const size_t bo = (size_t)blockIdx.z * 262144;
    const float* A = Am + bo;
    const float* B = Bm + bo;
    float* Cb = C + bo;
    const int m0 = blockIdx.y * 128, n0 = blockIdx.x * 128;
    const int t = threadIdx.x;
    const int tx = t & 15, ty = t >> 4;
    const int lr = t >> 1, lk = (t & 1) * 4;
    const int kr = t >> 5, nq = t & 31;

    float acc[8][8];
#pragma unroll
    for (int i = 0; i < 8; i++)
#pragma unroll
        for (int j = 0; j < 8; j++) acc[i][j] = 0.0f;

    const float* Ap = A + (size_t)(m0 + lr) * 512 + lk;

    for (int k0 = 0; k0 < 512; k0 += 8) {
        float4 a4 = *(const float4*)(Ap + k0);
        float4 b4 = *(const float4*)(B + (size_t)(k0 + kr) * 512 + n0 + nq * 4);
        As[lk + 0][lr] = a4.x; As[lk + 1][lr] = a4.y; As[lk + 2][lr] = a4.z; As[lk + 3][lr] = a4.w;
        *(float4*)&Bs[kr][nq * 4] = b4;
        __syncthreads();
#pragma unroll
        for (int k = 0; k < 8; k++) {
            float4 A0 = *(const float4*)&As[k][ty * 8];
            float4 A1v = *(const float4*)&As[k][ty * 8 + 4];
            float4 W0 = *(const float4*)&Bs[k][tx * 8];
            float4 W1v = *(const float4*)&Bs[k][tx * 8 + 4];
            float ar[8] = {A0.x, A0.y, A0.z, A0.w, A1v.x, A1v.y, A1v.z, A1v.w};
            float wr[8] = {W0.x, W0.y, W0.z, W0.w, W1v.x, W1v.y, W1v.z, W1v.w};
#pragma unroll
            for (int i = 0; i < 8; i++)
#pragma unroll
                for (int j = 0; j < 8; j++) acc[i][j] += ar[i] * wr[j];
        }
        __syncthreads();
    }
#pragma unroll
    for (int i = 0; i < 8; i++) {
        size_t row = (size_t)(m0 + ty * 8 + i) * 512 + n0 + tx * 8;
        float4 o0, o1;
        o0.x = acc[i][0]; o0.y = acc[i][1]; o0.z = acc[i][2]; o0.w = acc[i][3];
        o1.x = acc[i][4]; o1.y = acc[i][5]; o1.z = acc[i][6]; o1.w = acc[i][7];
        *(float4*)&Cb[row]     = o0;
        *(float4*)&Cb[row + 4] = o1;
    }
}

// ======================= copy observed rows into lstm_hidden ==================
__global__ void copy_obs_k(const float* __restrict__ obs, float* __restrict__ LH)
{
    size_t i = (size_t)blockIdx.x * blockDim.x + threadIdx.x;
    if (i < (size_t)Bn * OBSn * Hd) {
        size_t b = i >> 17;
        size_t rem = i & 131071;
        LH[b * 262144 + rem] = obs[i];
    }
}

// ================= persistent LSTM v2: W in registers, k-split GEMV ===========
// 128 blocks x 256 threads. Block owns 4 units (16 gate rows). Thread (row =
// t>>4, ks = t&15) holds W[grow, k in {32i+2ks, 32i+2ks+1}] in 32 registers.
// h in SMEM, row stride RROW=514 floats -> LDS.64 reads are conflict-free
// (lane residue 2*ks, half-warps broadcast-deduped). Partials reduced with
// shfl_xor over 16-lane groups. Cell state in a register. Grid barrier/step.
#define RROW 514
__global__ __launch_bounds__(256, 1) void lstm_persist(
    const float* __restrict__ obs, const float* __restrict__ XG,
    const float* __restrict__ Whh, float* __restrict__ LH)
{
    extern __shared__ float Hs[];                 // 64 x RROW floats
    __shared__ float gsm[16 * 66];

    const int t = threadIdx.x;
    const int ublk = blockIdx.x * 4;
    const unsigned nb = gridDim.x;

    const int row = t >> 4;            // 0..15 local gate row
    const int ks  = t & 15;            // k-slice id
    const int g = row >> 2, j = row & 3;

    // ---- W slice into registers (strided gather, once) ----
    float2 w[16];
    {
        const float* wr = Whh + (size_t)(g * 512 + ublk + j) * 512 + 2 * ks;
#pragma unroll
        for (int i = 0; i < 16; i++)
            w[i] = *(const float2*)(wr + i * 32);
    }

    // ---- pointwise role ----
    const int pm = t >> 2, pj = t & 3;
    float c_reg = obs[(size_t)pm * 131072 + 255 * 512 + ublk + pj];

    // ---- h copy role: lm = t & 63 (row), q = t >> 6 (quarter) ----
    const int lm = t & 63, q = t >> 6;

    for (int s = 0; s < 256; s++) {
        // prefetch gate biases from XG (hidden under GEMV)
        const float* xrow = XG + (size_t)(pm * 256 + s) * 2048 + ublk + pj;
        float xg0 = __ldcg(xrow);
        float xg1 = __ldcg(xrow + 512);
        float xg2 = __ldcg(xrow + 1024);
        float xg3 = __ldcg(xrow + 1536);

        // load h_prev [64 x 512] into SMEM
        {
            const float* hsrc; size_t hstr;
            if (s == 0) { hsrc = obs + 255 * 512; hstr = 131072; }
            else        { hsrc = LH + (size_t)(255 + s) * 512; hstr = 262144; }
            const float* src = hsrc + (size_t)lm * hstr + q * 128;
            float* dst = Hs + lm * RROW + q * 128;
#pragma unroll 8
            for (int i = 0; i < 32; i++) {
                float4 v = __ldcg((const float4*)(src + i * 4));
                *(float2*)(dst + i * 4)     = make_float2(v.x, v.y);
                *(float2*)(dst + i * 4 + 2) = make_float2(v.z, v.w);
            }
        }
        __syncthreads();

        // GEMV: 4 batches at a time for shfl pipelining
        for (int m0 = 0; m0 < 64; m0 += 4) {
            const float* h0 = Hs + (m0 + 0) * RROW + 2 * ks;
            const float* h1 = Hs + (m0 + 1) * RROW + 2 * ks;
            const float* h2 = Hs + (m0 + 2) * RROW + 2 * ks;
            const float* h3 = Hs + (m0 + 3) * RROW + 2 * ks;
            float a0 = 0.f, a1 = 0.f, a2 = 0.f, a3 = 0.f;
#pragma unroll
            for (int i = 0; i < 16; i++) {
                float2 x0 = *(const float2*)(h0 + i * 32);
                float2 x1 = *(const float2*)(h1 + i * 32);
                float2 x2 = *(const float2*)(h2 + i * 32);
                float2 x3 = *(const float2*)(h3 + i * 32);
                a0 += w[i].x * x0.x + w[i].y * x0.y;
                a1 += w[i].x * x1.x + w[i].y * x1.y;
                a2 += w[i].x * x2.x + w[i].y * x2.y;
                a3 += w[i].x * x3.x + w[i].y * x3.y;
            }
#pragma unroll
            for (int o = 8; o > 0; o >>= 1) {
                a0 += __shfl_xor_sync(0xffffffffu, a0, o);
                a1 += __shfl_xor_sync(0xffffffffu, a1, o);
                a2 += __shfl_xor_sync(0xffffffffu, a2, o);
                a3 += __shfl_xor_sync(0xffffffffu, a3, o);
            }
            if (ks == 0) {
                gsm[row * 66 + m0]     = a0;
                gsm[row * 66 + m0 + 1] = a1;
                gsm[row * 66 + m0 + 2] = a2;
                gsm[row * 66 + m0 + 3] = a3;
            }
        }
        __syncthreads();

        // pointwise gate math + h store
        {
            float gi = gsm[(0 + pj) * 66 + pm]  + xg0;
            float gf = gsm[(4 + pj) * 66 + pm]  + xg1;
            float gg = gsm[(8 + pj) * 66 + pm]  + xg2;
            float go = gsm[(12 + pj) * 66 + pm] + xg3;
            c_reg = sigmoidf_(gf) * c_reg + sigmoidf_(gi) * tanhf(gg);
            float hv = sigmoidf_(go) * tanhf(c_reg);
            LH[(size_t)pm * 262144 + (size_t)(256 + s) * 512 + ublk + pj] = hv;
        }

        // grid barrier (monotonic generation)
        __threadfence();
        __syncthreads();
        if (t == 0) {
            unsigned snap = g_bar_gen;
            unsigned old = atomicAdd(&g_bar_cnt, 1u);
            if (old == nb - 1u) {
                g_bar_cnt = 0;
                __threadfence();
                g_bar_gen = snap + 1u;
            } else {
                while (g_bar_gen == snap) { }
            }
            __threadfence();
        }
        __syncthreads();
    }
}

// ====================== fused GLU + LayerNorm (one block/row) =================
__global__ __launch_bounds__(256) void gluln_k(
    const float* __restrict__ a1, const float* __restrict__ a2,
    const float* __restrict__ y1, const float* __restrict__ y2,
    const float* __restrict__ gamma, const float* __restrict__ beta,
    float* __restrict__ outp, int splitY)
{
    __shared__ float red[8];
    const int r = blockIdx.x;
    const int t = threadIdx.x;
    const float* yp;
    if (splitY) {
        int b = r >> 9, tt = r & 511;
        yp = (tt < 256) ? (y1 + ((size_t)(b * 256 + tt)) * 512)
                        : (y2 + ((size_t)(b * 256 + tt - 256)) * 512);
    } else {
        yp = y1 + (size_t)r * 512;
    }
    const float* p1 = a1 + (size_t)r * 512;
    const float* p2 = a2 + (size_t)r * 512;
    float z0 = sigmoidf_(p1[t])       * p2[t]       + yp[t];
    float z1 = sigmoidf_(p1[t + 256]) * p2[t + 256] + yp[t + 256];

    float s = z0 + z1;
#pragma unroll
    for (int o = 16; o > 0; o >>= 1) s += __shfl_xor_sync(0xffffffffu, s, o);
    if ((t & 31) == 0) red[t >> 5] = s;
    __syncthreads();
    if (t < 32) {
        float a = (t < 8) ? red[t] : 0.0f;
#pragma unroll
        for (int o = 4; o > 0; o >>= 1) a += __shfl_xor_sync(0xffffffffu, a, o);
        if (t == 0) red[0] = a;
    }
    __syncthreads();
    float mu = red[0] * (1.0f / 512.0f);
    float d0 = z0 - mu, d1 = z1 - mu;
    float s2 = d0 * d0 + d1 * d1;
    __syncthreads();
#pragma unroll
    for (int o = 16; o > 0; o >>= 1) s2 += __shfl_xor_sync(0xffffffffu, s2, o);
    if ((t & 31) == 0) red[t >> 5] = s2;
    __syncthreads();
    if (t < 32) {
        float a = (t < 8) ? red[t] : 0.0f;
#pragma unroll
        for (int o = 4; o > 0; o >>= 1) a += __shfl_xor_sync(0xffffffffu, a, o);
        if (t == 0) red[0] = a;
    }
    __syncthreads();
    float inv = rsqrtf(red[0] * (1.0f / 512.0f) + 1e-5f);
    outp[(size_t)r * 512 + t]       = gamma[t]       * d0 * inv + beta[t];
    outp[(size_t)r * 512 + t + 256] = gamma[t + 256] * d1 * inv + beta[t + 256];
}

// ========================= row softmax over 512 cols ==========================
__global__ __launch_bounds__(256) void softmax_k(
    const float* __restrict__ S, float* __restrict__ A)
{
    __shared__ float red[8];
    const int r = blockIdx.x;
    const int t = threadIdx.x;
    const float* p = S + (size_t)r * 512;
    float v0 = p[t], v1 = p[t + 256];
    float m = fmaxf(v0, v1);
#pragma unroll
    for (int o = 16; o > 0; o >>= 1) m = fmaxf(m, __shfl_xor_sync(0xffffffffu, m, o));
    if ((t & 31) == 0) red[t >> 5] = m;
    __syncthreads();
    if (t < 32) {
        float a = (t < 8) ? red[t] : -3.4e38f;
#pragma unroll
        for (int o = 4; o > 0; o >>= 1) a = fmaxf(a, __shfl_xor_sync(0xffffffffu, a, o));
        if (t == 0) red[0] = a;
    }
    __syncthreads();
    float mx = red[0];
    float e0 = expf(v0 - mx), e1 = expf(v1 - mx);
    float s = e0 + e1;
    __syncthreads();
#pragma unroll
    for (int o = 16; o > 0; o >>= 1) s += __shfl_xor_sync(0xffffffffu, s, o);
    if ((t & 31) == 0) red[t >> 5] = s;
    __syncthreads();
    if (t < 32) {
        float a = (t < 8) ? red[t] : 0.0f;
#pragma unroll
        for (int o = 4; o > 0; o >>= 1) a += __shfl_xor_sync(0xffffffffu, a, o);
        if (t == 0) red[0] = a;
    }
    __syncthreads();
    float inv = 1.0f / red[0];
    A[(size_t)r * 512 + t]       = e0 * inv;
    A[(size_t)r * 512 + t + 256] = e1 * inv;
}

// ================================= host =======================================
extern "C" void kernel_launch(void* const* d_in, const int* in_sizes, int n_in,
                              void* d_out, int out_size)
{
    const float* obs   = (const float*)d_in[0];
    const float* fut   = (const float*)d_in[1];
    const float* W_ih  = (const float*)d_in[2];
    const float* W_hh  = (const float*)d_in[3];
    const float* b_ih  = (const float*)d_in[4];
    const float* b_hh  = (const float*)d_in[5];
    const float* g1W1  = (const float*)d_in[6];
    const float* g1b1  = (const float*)d_in[7];
    const float* g1W2  = (const float*)d_in[8];
    const float* g1b2  = (const float*)d_in[9];
    const float* g1g   = (const float*)d_in[10];
    const float* g1b   = (const float*)d_in[11];
    const float* Wq    = (const float*)d_in[12];
    const float* bq    = (const float*)d_in[13];
    const float* Wk    = (const float*)d_in[14];
    const float* bk    = (const float*)d_in[15];
    const float* Wv    = (const float*)d_in[16];
    const float* bv    = (const float*)d_in[17];
    const float* Wo    = (const float*)d_in[18];
    const float* bo    = (const float*)d_in[19];
    const float* g2W1  = (const float*)d_in[20];
    const float* g2b1  = (const float*)d_in[21];
    const float* g2W2  = (const float*)d_in[22];
    const float* g2b2  = (const float*)d_in[23];
    const float* g2g   = (const float*)d_in[24];
    const float* g2b   = (const float*)d_in[25];

    float* out       = (float*)d_out;
    float* glu_delta = out;
    float* glu_phi   = out + (size_t)OUT1;
    float* attn      = out + (size_t)2 * OUT1;

    float *XG, *LH, *A1, *A2, *Qb, *Kb, *Vb;
    cudaGetSymbolAddress((void**)&XG, d_XG);
    cudaGetSymbolAddress((void**)&LH, d_LH);
    cudaGetSymbolAddress((void**)&A1, d_A1);
    cudaGetSymbolAddress((void**)&A2, d_A2);
    cudaGetSymbolAddress((void**)&Qb, d_Qb);
    cudaGetSymbolAddress((void**)&Kb, d_Kb);
    cudaGetSymbolAddress((void**)&Vb, d_Vb);

    // 1. X_gates = fut @ W_ih^T + (b_ih + b_hh)
    gemm_tn<<<dim3(G4 / 128, BF / 128), 256>>>(fut, W_ih, b_ih, b_hh, XG, BF, G4, Hd);

    // 2. lstm_hidden[:, :256, :] = vsn_observed
    copy_obs_k<<<(Bn * OBSn * Hd + 255) / 256, 256>>>(obs, LH);

    // 3. persistent LSTM over all 256 steps
    {
        const int smem = 64 * RROW * 4;   // 131584 bytes
        cudaFuncSetAttribute(lstm_persist, cudaFuncAttributeMaxDynamicSharedMemorySize, smem);
        lstm_persist<<<128, 256, smem>>>(obs, XG, W_hh, LH);
    }

    // 4. GLU-LN #1 -> glu_phi
    gemm_tn<<<dim3(4, 256), 256>>>(LH, g1W1, g1b1, nullptr, A1, BT, Hd, Hd);
    gemm_tn<<<dim3(4, 256), 256>>>(LH, g1W2, g1b2, nullptr, A2, BT, Hd, Hd);
    gluln_k<<<BT, 256>>>(A1, A2, obs, fut, g1g, g1b, glu_phi, 1);

    // 5. QKV
    gemm_tn<<<dim3(4, 256), 256>>>(glu_phi, Wq, bq, nullptr, Qb, BT, Hd, Hd);
    gemm_tn<<<dim3(4, 256), 256>>>(glu_phi, Wk, bk, nullptr, Kb, BT, Hd, Hd);
    gemm_tn<<<dim3(4, 256), 256>>>(glu_phi, Wv, bv, nullptr, Vb, BT, Hd, Hd);

    // 6. scores (reuse XG) + softmax -> attn
    gemm_tn_scores<<<dim3(4, 4, 64), 256>>>(Qb, Kb, XG, 0.04419417382415922f);
    softmax_k<<<BT, 256>>>(XG, attn);

    // 7. attn @ V -> reuse Qb; projection -> reuse Kb
    gemm_nn_b<<<dim3(4, 4, 64), 256>>>(attn, Vb, Qb);
    gemm_tn<<<dim3(4, 256), 256>>>(Qb, Wo, bo, nullptr, Kb, BT, Hd, Hd);

    // 8. GLU-LN #2 -> glu_delta
    gemm_tn<<<dim3(4, 256), 256>>>(Kb, g2W1, g2b1, nullptr, A1, BT, Hd, Hd);
    gemm_tn<<<dim3(4, 256), 256>>>(Kb, g2W2, g2b2, nullptr, A2, BT, Hd, Hd);
    gluln_k<<<BT, 256>>>(A1, A2, glu_phi, nullptr, g2g, g2b, glu_delta, 0);
}

// round 5
// speedup vs baseline: 1.3503x; 1.1217x over previous
#include <cuda_runtime.h>
#include <cstdint>
#include <cstddef>

// Problem dims
#define Hd    512
#define Bn    64
#define OBSn  256
#define FUTn  256
#define Tn    512
#define G4    2048
#define BT    32768          // Bn*Tn
#define BF    16384          // Bn*FUTn
#define OUT1  16777216       // Bn*Tn*Hd

// ---------------- scratch (no allocation allowed; device globals) -------------
__device__ float d_XG[(size_t)BF * G4];        // x-gates, reused for attention scores
__device__ float d_LH[(size_t)BT * Hd];        // lstm_hidden (concat observed + lstm h)
__device__ float d_A1[(size_t)BT * Hd];
__device__ float d_A2[(size_t)BT * Hd];
__device__ float d_Qb[(size_t)BT * Hd];
__device__ float d_Kb[(size_t)BT * Hd];
__device__ float d_Vb[(size_t)BT * Hd];

// grid-barrier state for persistent LSTM (monotonic generation: replay-safe)
__device__ unsigned g_bar_cnt = 0;
__device__ volatile unsigned g_bar_gen = 0;

__device__ __forceinline__ float sigmoidf_(float x) { return 1.0f / (1.0f + expf(-x)); }

// ======================= TN GEMM: C = A[M,K] @ W[N,K]^T + b1 + b2 =============
__global__ __launch_bounds__(256) void gemm_tn(
    const float* __restrict__ A, const float* __restrict__ W,
    const float* __restrict__ b1, const float* __restrict__ b2,
    float* __restrict__ C, int M, int N, int K)
{
    __shared__ float As[8][132];
    __shared__ float Ws[8][132];
    const int m0 = blockIdx.y * 128, n0 = blockIdx.x * 128;
    const int t  = threadIdx.x;
    const int tx = t & 15, ty = t >> 4;
    const int lr = t >> 1, lk = (t & 1) * 4;

    float acc[8][8];
#pragma unroll
    for (int i = 0; i < 8; i++)
#pragma unroll
        for (int j = 0; j < 8; j++) acc[i][j] = 0.0f;

    const float* Ap = A + (size_t)(m0 + lr) * K + lk;
    const float* Wp = W + (size_t)(n0 + lr) * K + lk;

    for (int k0 = 0; k0 < K; k0 += 8) {
        float4 a4 = *(const float4*)(Ap + k0);
        float4 w4 = *(const float4*)(Wp + k0);
        As[lk + 0][lr] = a4.x; As[lk + 1][lr] = a4.y; As[lk + 2][lr] = a4.z; As[lk + 3][lr] = a4.w;
        Ws[lk + 0][lr] = w4.x; Ws[lk + 1][lr] = w4.y; Ws[lk + 2][lr] = w4.z; Ws[lk + 3][lr] = w4.w;
        __syncthreads();
#pragma unroll
        for (int k = 0; k < 8; k++) {
            float4 A0 = *(const float4*)&As[k][ty * 8];
            float4 A1v = *(const float4*)&As[k][ty * 8 + 4];
            float4 W0 = *(const float4*)&Ws[k][tx * 8];
            float4 W1v = *(const float4*)&Ws[k][tx * 8 + 4];
            float ar[8] = {A0.x, A0.y, A0.z, A0.w, A1v.x, A1v.y, A1v.z, A1v.w};
            float wr[8] = {W0.x, W0.y, W0.z, W0.w, W1v.x, W1v.y, W1v.z, W1v.w};
#pragma unroll
            for (int i = 0; i < 8; i++)
#pragma unroll
                for (int j = 0; j < 8; j++) acc[i][j] += ar[i] * wr[j];
        }
        __syncthreads();
    }

    float bb[8];
#pragma unroll
    for (int j = 0; j < 8; j++) {
        int n = n0 + tx * 8 + j;
        float v = b1 ? b1[n] : 0.0f;
        if (b2) v += b2[n];
        bb[j] = v;
    }
#pragma unroll
    for (int i = 0; i < 8; i++) {
        size_t row = (size_t)(m0 + ty * 8 + i) * N + n0 + tx * 8;
        float4 o0, o1;
        o0.x = acc[i][0] + bb[0]; o0.y = acc[i][1] + bb[1];
        o0.z = acc[i][2] + bb[2]; o0.w = acc[i][3] + bb[3];
        o1.x = acc[i][4] + bb[4]; o1.y = acc[i][5] + bb[5];
        o1.z = acc[i][6] + bb[6]; o1.w = acc[i][7] + bb[7];
        *(float4*)&C[row]     = o0;
        *(float4*)&C[row + 4] = o1;
    }
}

// ============== batched scores: S = scale * Q Kt^T with causal mask ===========
__global__ __launch_bounds__(256) void gemm_tn_scores(
    const float* __restrict__ Qm, const float* __restrict__ Km,
    float* __restrict__ C, float scale)
{
    __shared__ float As[8][132];
    __shared__ float Ws[8][132];
    const size_t bo = (size_t)blockIdx.z * 262144;
    const float* A = Qm + bo;
    const float* W = Km + bo;
    float* Cb = C + bo;
    const int m0 = blockIdx.y * 128, n0 = blockIdx.x * 128;
    const int t = threadIdx.x;
    const int tx = t & 15, ty = t >> 4;
    const int lr = t >> 1, lk = (t & 1) * 4;

    float acc[8][8];
#pragma unroll
    for (int i = 0; i < 8; i++)
#pragma unroll
        for (int j = 0; j < 8; j++) acc[i][j] = 0.0f;

    const float* Ap = A + (size_t)(m0 + lr) * 512 + lk;
    const float* Wp = W + (size_t)(n0 + lr) * 512 + lk;

    for (int k0 = 0; k0 < 512; k0 += 8) {
        float4 a4 = *(const float4*)(Ap + k0);
        float4 w4 = *(const float4*)(Wp + k0);
        As[lk + 0][lr] = a4.x; As[lk + 1][lr] = a4.y; As[lk + 2][lr] = a4.z; As[lk + 3][lr] = a4.w;
        Ws[lk + 0][lr] = w4.x; Ws[lk + 1][lr] = w4.y; Ws[lk + 2][lr] = w4.z; Ws[lk + 3][lr] = w4.w;
        __syncthreads();
#pragma unroll
        for (int k = 0; k < 8; k++) {
            float4 A0 = *(const float4*)&As[k][ty * 8];
            float4 A1v = *(const float4*)&As[k][ty * 8 + 4];
            float4 W0 = *(const float4*)&Ws[k][tx * 8];
            float4 W1v = *(const float4*)&Ws[k][tx * 8 + 4];
            float ar[8] = {A0.x, A0.y, A0.z, A0.w, A1v.x, A1v.y, A1v.z, A1v.w};
            float wr[8] = {W0.x, W0.y, W0.z, W0.w, W1v.x, W1v.y, W1v.z, W1v.w};
#pragma unroll
            for (int i = 0; i < 8; i++)
#pragma unroll
                for (int j = 0; j < 8; j++) acc[i][j] += ar[i] * wr[j];
        }
        __syncthreads();
    }
#pragma unroll
    for (int i = 0; i < 8; i++) {
        int q = m0 + ty * 8 + i;
#pragma unroll
        for (int j = 0; j < 8; j++) {
            int kk = n0 + tx * 8 + j;
            float v = acc[i][j] * scale;
            if (kk > q) v = -1e30f;
            Cb[(size_t)q * 512 + kk] = v;
        }
    }
}

// ==================== batched NN GEMM: O = attn[512,512] @ V[512,512] =========
__global__ __launch_bounds__(256) void gemm_nn_b(
    const float* __restrict__ Am, const float* __restrict__ Bm, float* __restrict__ C)
{
    __shared__ float As[8][132];
    __shared__ float Bs[8][128];
    const size_t bo = (size_t)blockIdx.z * 262144;
    const float* A = Am + bo;
    const float* B = Bm + bo;
    float* Cb = C + bo;
    const int m0 = blockIdx.y * 128, n0 = blockIdx.x * 128;
    const int t = threadIdx.x;
    const int tx = t & 15, ty = t >> 4;
    const int lr = t >> 1, lk = (t & 1) * 4;
    const int kr = t >> 5, nq = t & 31;

    float acc[8][8];
#pragma unroll
    for (int i = 0; i < 8; i++)
#pragma unroll
        for (int j = 0; j < 8; j++) acc[i][j] = 0.0f;

    const float* Ap = A + (size_t)(m0 + lr) * 512 + lk;

    for (int k0 = 0; k0 < 512; k0 += 8) {
        float4 a4 = *(const float4*)(Ap + k0);
        float4 b4 = *(const float4*)(B + (size_t)(k0 + kr) * 512 + n0 + nq * 4);
        As[lk + 0][lr] = a4.x; As[lk + 1][lr] = a4.y; As[lk + 2][lr] = a4.z; As[lk + 3][lr] = a4.w;
        *(float4*)&Bs[kr][nq * 4] = b4;
        __syncthreads();
#pragma unroll
        for (int k = 0; k < 8; k++) {
            float4 A0 = *(const float4*)&As[k][ty * 8];
            float4 A1v = *(const float4*)&As[k][ty * 8 + 4];
            float4 W0 = *(const float4*)&Bs[k][tx * 8];
            float4 W1v = *(const float4*)&Bs[k][tx * 8 + 4];
            float ar[8] = {A0.x, A0.y, A0.z, A0.w, A1v.x, A1v.y, A1v.z, A1v.w};
            float wr[8] = {W0.x, W0.y, W0.z, W0.w, W1v.x, W1v.y, W1v.z, W1v.w};
#pragma unroll
            for (int i = 0; i < 8; i++)
#pragma unroll
                for (int j = 0; j < 8; j++) acc[i][j] += ar[i] * wr[j];
        }
        __syncthreads();
    }
#pragma unroll
    for (int i = 0; i < 8; i++) {
        size_t row = (size_t)(m0 + ty * 8 + i) * 512 + n0 + tx * 8;
        float4 o0, o1;
        o0.x = acc[i][0]; o0.y = acc[i][1]; o0.z = acc[i][2]; o0.w = acc[i][3];
        o1.x = acc[i][4]; o1.y = acc[i][5]; o1.z = acc[i][6]; o1.w = acc[i][7];
        *(float4*)&Cb[row]     = o0;
        *(float4*)&Cb[row + 4] = o1;
    }
}

// ======================= copy observed rows into lstm_hidden ==================
__global__ void copy_obs_k(const float* __restrict__ obs, float* __restrict__ LH)
{
    size_t i = (size_t)blockIdx.x * blockDim.x + threadIdx.x;
    if (i < (size_t)Bn * OBSn * Hd) {
        size_t b = i >> 17;
        size_t rem = i & 131071;
        LH[b * 262144 + rem] = obs[i];
    }
}

// ============ persistent LSTM v3b: lane=batch, broadcast W, no reductions =====
// 128 blocks x 256 threads. Block owns 4 units (16 gate rows). Warp wid ->
// (gate g = wid>>1, batch-half bh = wid&1); lane = batch within half. Each lane
// accumulates 4 gate-rows for its batch -> complete in registers, no reduction.
// Hs row stride 516 floats: lane L at float index 516L + k -> bank (4L+k)%32;
// each 8-lane LDS.128 phase covers all 32 banks -> conflict-free. W broadcast.
#define HSTRIDE 516
#define WSTRIDE 512
__global__ __launch_bounds__(256, 1) void lstm_persist(
    const float* __restrict__ obs, const float* __restrict__ XG,
    const float* __restrict__ Whh, float* __restrict__ LH)
{
    extern __shared__ float sh[];
    float* Hs = sh;                        // 64 x HSTRIDE
    float* Ws = sh + 64 * HSTRIDE;         // 16 x WSTRIDE
    __shared__ float gsm[4 * 64 * 4];      // [gate][batch][unit]

    const int t = threadIdx.x;
    const int ublk = blockIdx.x * 4;
    const unsigned nb = gridDim.x;

    // ---- load W into SMEM once: 16 rows x 512 ----
    for (int idx = t; idx < 16 * 128; idx += 256) {
        int row = idx >> 7, q = idx & 127;
        int g = row >> 2, j = row & 3;
        float4 v = *(const float4*)(Whh + (size_t)(g * 512 + ublk + j) * 512 + q * 4);
        *(float4*)(Ws + row * WSTRIDE + q * 4) = v;
    }

    // ---- warp roles for GEMV ----
    const int wid = t >> 5, lane = t & 31;
    const int g = wid >> 1, bh = wid & 1;
    const int batch = bh * 32 + lane;

    // ---- pointwise role ----
    const int pb = t >> 2, pj = t & 3;
    float c_reg = obs[(size_t)pb * 131072 + 255 * 512 + ublk + pj];

    // ---- h-copy role ----
    const int lm = t & 63, q4 = t >> 6;

    for (int s = 0; s < 256; s++) {
        // XG prefetch (consumed after GEMV; hides DRAM latency)
        const float* xrow = XG + (size_t)(pb * 256 + s) * 2048 + ublk + pj;
        float xg0 = __ldcg(xrow);
        float xg1 = __ldcg(xrow + 512);
        float xg2 = __ldcg(xrow + 1024);
        float xg3 = __ldcg(xrow + 1536);

        // load h_prev [64 x 512] into Hs (row stride HSTRIDE)
        {
            const float* hsrc; size_t hstr;
            if (s == 0) { hsrc = obs + 255 * 512; hstr = 131072; }
            else        { hsrc = LH + (size_t)(255 + s) * 512; hstr = 262144; }
            const float4* src = (const float4*)(hsrc + (size_t)lm * hstr) + q4 * 32;
            float4* dst = (float4*)(Hs + lm * HSTRIDE) + q4 * 32;
#pragma unroll
            for (int i = 0; i < 32; i += 8) {
                float4 v0 = __ldcg(src + i + 0);
                float4 v1 = __ldcg(src + i + 1);
                float4 v2 = __ldcg(src + i + 2);
                float4 v3 = __ldcg(src + i + 3);
                float4 v4 = __ldcg(src + i + 4);
                float4 v5 = __ldcg(src + i + 5);
                float4 v6 = __ldcg(src + i + 6);
                float4 v7 = __ldcg(src + i + 7);
                dst[i + 0] = v0; dst[i + 1] = v1; dst[i + 2] = v2; dst[i + 3] = v3;
                dst[i + 4] = v4; dst[i + 5] = v5; dst[i + 6] = v6; dst[i + 7] = v7;
            }
        }
        __syncthreads();

        // GEMV: lane computes 4 gate-rows (gate g, units 0..3) for its batch
        {
            const float* xp = Hs + batch * HSTRIDE;
            const float* wp = Ws + (g * 4) * WSTRIDE;
            float a0 = 0.f, a1 = 0.f, a2 = 0.f, a3 = 0.f;
#pragma unroll 8
            for (int k0 = 0; k0 < 512; k0 += 4) {
                float4 xv = *(const float4*)(xp + k0);
                float4 w0 = *(const float4*)(wp + k0);
                float4 w1 = *(const float4*)(wp + WSTRIDE + k0);
                float4 w2 = *(const float4*)(wp + 2 * WSTRIDE + k0);
                float4 w3 = *(const float4*)(wp + 3 * WSTRIDE + k0);
                a0 += xv.x * w0.x + xv.y * w0.y + xv.z * w0.z + xv.w * w0.w;
                a1 += xv.x * w1.x + xv.y * w1.y + xv.z * w1.z + xv.w * w1.w;
                a2 += xv.x * w2.x + xv.y * w2.y + xv.z * w2.z + xv.w * w2.w;
                a3 += xv.x * w3.x + xv.y * w3.y + xv.z * w3.z + xv.w * w3.w;
            }
            float4 o; o.x = a0; o.y = a1; o.z = a2; o.w = a3;
            *(float4*)(gsm + (g * 64 + batch) * 4) = o;
        }
        __syncthreads();

        // pointwise gate math + h store
        {
            float gi = gsm[(0 * 64 + pb) * 4 + pj] + xg0;
            float gf = gsm[(1 * 64 + pb) * 4 + pj] + xg1;
            float gg = gsm[(2 * 64 + pb) * 4 + pj] + xg2;
            float go = gsm[(3 * 64 + pb) * 4 + pj] + xg3;
            c_reg = sigmoidf_(gf) * c_reg + sigmoidf_(gi) * tanhf(gg);
            float hv = sigmoidf_(go) * tanhf(c_reg);
            LH[(size_t)pb * 262144 + (size_t)(256 + s) * 512 + ublk + pj] = hv;
        }

        // grid barrier (monotonic generation, nanosleep backoff)
        __threadfence();
        __syncthreads();
        if (t == 0) {
            unsigned snap = g_bar_gen;
            unsigned old = atomicAdd(&g_bar_cnt, 1u);
            if (old == nb - 1u) {
                g_bar_cnt = 0;
                __threadfence();
                g_bar_gen = snap + 1u;
            } else {
                while (g_bar_gen == snap) __nanosleep(64);
            }
            __threadfence();
        }
        __syncthreads();
    }
}

// ====================== fused GLU + LayerNorm (one block/row) =================
__global__ __launch_bounds__(256) void gluln_k(
    const float* __restrict__ a1, const float* __restrict__ a2,
    const float* __restrict__ y1, const float* __restrict__ y2,
    const float* __restrict__ gamma, const float* __restrict__ beta,
    float* __restrict__ outp, int splitY)
{
    __shared__ float red[8];
    const int r = blockIdx.x;
    const int t = threadIdx.x;
    const float* yp;
    if (splitY) {
        int b = r >> 9, tt = r & 511;
        yp = (tt < 256) ? (y1 + ((size_t)(b * 256 + tt)) * 512)
                        : (y2 + ((size_t)(b * 256 + tt - 256)) * 512);
    } else {
        yp = y1 + (size_t)r * 512;
    }
    const float* p1 = a1 + (size_t)r * 512;
    const float* p2 = a2 + (size_t)r * 512;
    float z0 = sigmoidf_(p1[t])       * p2[t]       + yp[t];
    float z1 = sigmoidf_(p1[t + 256]) * p2[t + 256] + yp[t + 256];

    float s = z0 + z1;
#pragma unroll
    for (int o = 16; o > 0; o >>= 1) s += __shfl_xor_sync(0xffffffffu, s, o);
    if ((t & 31) == 0) red[t >> 5] = s;
    __syncthreads();
    if (t < 32) {
        float a = (t < 8) ? red[t] : 0.0f;
#pragma unroll
        for (int o = 4; o > 0; o >>= 1) a += __shfl_xor_sync(0xffffffffu, a, o);
        if (t == 0) red[0] = a;
    }
    __syncthreads();
    float mu = red[0] * (1.0f / 512.0f);
    float d0 = z0 - mu, d1 = z1 - mu;
    float s2 = d0 * d0 + d1 * d1;
    __syncthreads();
#pragma unroll
    for (int o = 16; o > 0; o >>= 1) s2 += __shfl_xor_sync(0xffffffffu, s2, o);
    if ((t & 31) == 0) red[t >> 5] = s2;
    __syncthreads();
    if (t < 32) {
        float a = (t < 8) ? red[t] : 0.0f;
#pragma unroll
        for (int o = 4; o > 0; o >>= 1) a += __shfl_xor_sync(0xffffffffu, a, o);
        if (t == 0) red[0] = a;
    }
    __syncthreads();
    float inv = rsqrtf(red[0] * (1.0f / 512.0f) + 1e-5f);
    outp[(size_t)r * 512 + t]       = gamma[t]       * d0 * inv + beta[t];
    outp[(size_t)r * 512 + t + 256] = gamma[t + 256] * d1 * inv + beta[t + 256];
}

// ========================= row softmax over 512 cols ==========================
__global__ __launch_bounds__(256) void softmax_k(
    const float* __restrict__ S, float* __restrict__ A)
{
    __shared__ float red[8];
    const int r = blockIdx.x;
    const int t = threadIdx.x;
    const float* p = S + (size_t)r * 512;
    float v0 = p[t], v1 = p[t + 256];
    float m = fmaxf(v0, v1);
#pragma unroll
    for (int o = 16; o > 0; o >>= 1) m = fmaxf(m, __shfl_xor_sync(0xffffffffu, m, o));
    if ((t & 31) == 0) red[t >> 5] = m;
    __syncthreads();
    if (t < 32) {
        float a = (t < 8) ? red[t] : -3.4e38f;
#pragma unroll
        for (int o = 4; o > 0; o >>= 1) a = fmaxf(a, __shfl_xor_sync(0xffffffffu, a, o));
        if (t == 0) red[0] = a;
    }
    __syncthreads();
    float mx = red[0];
    float e0 = expf(v0 - mx), e1 = expf(v1 - mx);
    float s = e0 + e1;
    __syncthreads();
#pragma unroll
    for (int o = 16; o > 0; o >>= 1) s += __shfl_xor_sync(0xffffffffu, s, o);
    if ((t & 31) == 0) red[t >> 5] = s;
    __syncthreads();
    if (t < 32) {
        float a = (t < 8) ? red[t] : 0.0f;
#pragma unroll
        for (int o = 4; o > 0; o >>= 1) a += __shfl_xor_sync(0xffffffffu, a, o);
        if (t == 0) red[0] = a;
    }
    __syncthreads();
    float inv = 1.0f / red[0];
    A[(size_t)r * 512 + t]       = e0 * inv;
    A[(size_t)r * 512 + t + 256] = e1 * inv;
}

// ================================= host =======================================
extern "C" void kernel_launch(void* const* d_in, const int* in_sizes, int n_in,
                              void* d_out, int out_size)
{
    const float* obs   = (const float*)d_in[0];
    const float* fut   = (const float*)d_in[1];
    const float* W_ih  = (const float*)d_in[2];
    const float* W_hh  = (const float*)d_in[3];
    const float* b_ih  = (const float*)d_in[4];
    const float* b_hh  = (const float*)d_in[5];
    const float* g1W1  = (const float*)d_in[6];
    const float* g1b1  = (const float*)d_in[7];
    const float* g1W2  = (const float*)d_in[8];
    const float* g1b2  = (const float*)d_in[9];
    const float* g1g   = (const float*)d_in[10];
    const float* g1b   = (const float*)d_in[11];
    const float* Wq    = (const float*)d_in[12];
    const float* bq    = (const float*)d_in[13];
    const float* Wk    = (const float*)d_in[14];
    const float* bk    = (const float*)d_in[15];
    const float* Wv    = (const float*)d_in[16];
    const float* bv    = (const float*)d_in[17];
    const float* Wo    = (const float*)d_in[18];
    const float* bo    = (const float*)d_in[19];
    const float* g2W1  = (const float*)d_in[20];
    const float* g2b1  = (const float*)d_in[21];
    const float* g2W2  = (const float*)d_in[22];
    const float* g2b2  = (const float*)d_in[23];
    const float* g2g   = (const float*)d_in[24];
    const float* g2b   = (const float*)d_in[25];

    float* out       = (float*)d_out;
    float* glu_delta = out;
    float* glu_phi   = out + (size_t)OUT1;
    float* attn      = out + (size_t)2 * OUT1;

    float *XG, *LH, *A1, *A2, *Qb, *Kb, *Vb;
    cudaGetSymbolAddress((void**)&XG, d_XG);
    cudaGetSymbolAddress((void**)&LH, d_LH);
    cudaGetSymbolAddress((void**)&A1, d_A1);
    cudaGetSymbolAddress((void**)&A2, d_A2);
    cudaGetSymbolAddress((void**)&Qb, d_Qb);
    cudaGetSymbolAddress((void**)&Kb, d_Kb);
    cudaGetSymbolAddress((void**)&Vb, d_Vb);

    // 1. X_gates = fut @ W_ih^T + (b_ih + b_hh)
    gemm_tn<<<dim3(G4 / 128, BF / 128), 256>>>(fut, W_ih, b_ih, b_hh, XG, BF, G4, Hd);

    // 2. lstm_hidden[:, :256, :] = vsn_observed
    copy_obs_k<<<(Bn * OBSn * Hd + 255) / 256, 256>>>(obs, LH);

    // 3. persistent LSTM over all 256 steps
    {
        const int smem = (64 * HSTRIDE + 16 * WSTRIDE) * 4;   // 164864 bytes
        cudaFuncSetAttribute(lstm_persist, cudaFuncAttributeMaxDynamicSharedMemorySize, smem);
        lstm_persist<<<128, 256, smem>>>(obs, XG, W_hh, LH);
    }

    // 4. GLU-LN #1 -> glu_phi
    gemm_tn<<<dim3(4, 256), 256>>>(LH, g1W1, g1b1, nullptr, A1, BT, Hd, Hd);
    gemm_tn<<<dim3(4, 256), 256>>>(LH, g1W2, g1b2, nullptr, A2, BT, Hd, Hd);
    gluln_k<<<BT, 256>>>(A1, A2, obs, fut, g1g, g1b, glu_phi, 1);

    // 5. QKV
    gemm_tn<<<dim3(4, 256), 256>>>(glu_phi, Wq, bq, nullptr, Qb, BT, Hd, Hd);
    gemm_tn<<<dim3(4, 256), 256>>>(glu_phi, Wk, bk, nullptr, Kb, BT, Hd, Hd);
    gemm_tn<<<dim3(4, 256), 256>>>(glu_phi, Wv, bv, nullptr, Vb, BT, Hd, Hd);

    // 6. scores (reuse XG) + softmax -> attn
    gemm_tn_scores<<<dim3(4, 4, 64), 256>>>(Qb, Kb, XG, 0.04419417382415922f);
    softmax_k<<<BT, 256>>>(XG, attn);

    // 7. attn @ V -> reuse Qb; projection -> reuse Kb
    gemm_nn_b<<<dim3(4, 4, 64), 256>>>(attn, Vb, Qb);
    gemm_tn<<<dim3(4, 256), 256>>>(Qb, Wo, bo, nullptr, Kb, BT, Hd, Hd);

    // 8. GLU-LN #2 -> glu_delta
    gemm_tn<<<dim3(4, 256), 256>>>(Kb, g2W1, g2b1, nullptr, A1, BT, Hd, Hd);
    gemm_tn<<<dim3(4, 256), 256>>>(Kb, g2W2, g2b2, nullptr, A2, BT, Hd, Hd);
    gluln_k<<<BT, 256>>>(A1, A2, glu_phi, nullptr, g2g, g2b, glu_delta, 0);
}

// round 6
// speedup vs baseline: 1.8454x; 1.3667x over previous
#include <cuda_runtime.h>
#include <cstdint>
#include <cstddef>

// Problem dims
#define Hd    512
#define Bn    64
#define OBSn  256
#define FUTn  256
#define Tn    512
#define G4    2048
#define BT    32768          // Bn*Tn
#define BF    16384          // Bn*FUTn
#define OUT1  16777216       // Bn*Tn*Hd

// ---------------- scratch (no allocation allowed; device globals) -------------
__device__ float d_XG[(size_t)BF * G4];
__device__ float d_LH[(size_t)BT * Hd];
__device__ float d_A1[(size_t)BT * Hd];
__device__ float d_A2[(size_t)BT * Hd];
__device__ float d_Qb[(size_t)BT * Hd];
__device__ float d_Kb[(size_t)BT * Hd];
__device__ float d_Vb[(size_t)BT * Hd];

__device__ unsigned g_bar_cnt = 0;
__device__ volatile unsigned g_bar_gen = 0;

__device__ __forceinline__ float sigmoidf_(float x) { return 1.0f / (1.0f + expf(-x)); }

// ====== TN GEMM v2: double-buffered, conflict-free split-4 fragments ==========
// C = A[M,K] @ W[N,K]^T + b1 + b2. 128x128 tile, BK=8, 256 thr, 8x8 micro.
// Thread rows: {ty*4..+3, 64+ty*4..+3}; cols: {tx*4..+3, 64+tx*4..+3}.
__global__ __launch_bounds__(256) void gemm_tn(
    const float* __restrict__ A, const float* __restrict__ W,
    const float* __restrict__ b1, const float* __restrict__ b2,
    float* __restrict__ C, int M, int N, int K)
{
    __shared__ float As[2][8][132];
    __shared__ float Ws[2][8][132];
    const int m0 = blockIdx.y * 128, n0 = blockIdx.x * 128;
    const int t  = threadIdx.x;
    const int tx = t & 15, ty = t >> 4;
    const int lr = t >> 1, lk = (t & 1) * 4;

    float acc[8][8];
#pragma unroll
    for (int i = 0; i < 8; i++)
#pragma unroll
        for (int j = 0; j < 8; j++) acc[i][j] = 0.0f;

    const float* Ap = A + (size_t)(m0 + lr) * K + lk;
    const float* Wp = W + (size_t)(n0 + lr) * K + lk;

    {   // prologue: stage 0
        float4 a4 = *(const float4*)(Ap);
        float4 w4 = *(const float4*)(Wp);
        As[0][lk + 0][lr] = a4.x; As[0][lk + 1][lr] = a4.y;
        As[0][lk + 2][lr] = a4.z; As[0][lk + 3][lr] = a4.w;
        Ws[0][lk + 0][lr] = w4.x; Ws[0][lk + 1][lr] = w4.y;
        Ws[0][lk + 2][lr] = w4.z; Ws[0][lk + 3][lr] = w4.w;
    }
    __syncthreads();

    int st = 0;
    for (int k0 = 0; k0 < K; k0 += 8) {
        float4 an, wn;
        const bool more = (k0 + 8) < K;
        if (more) {
            an = *(const float4*)(Ap + k0 + 8);
            wn = *(const float4*)(Wp + k0 + 8);
        }
#pragma unroll
        for (int k = 0; k < 8; k++) {
            float4 A0 = *(const float4*)&As[st][k][ty * 4];
            float4 A1 = *(const float4*)&As[st][k][64 + ty * 4];
            float4 W0 = *(const float4*)&Ws[st][k][tx * 4];
            float4 W1 = *(const float4*)&Ws[st][k][64 + tx * 4];
            float ar[8] = {A0.x, A0.y, A0.z, A0.w, A1.x, A1.y, A1.z, A1.w};
            float wr[8] = {W0.x, W0.y, W0.z, W0.w, W1.x, W1.y, W1.z, W1.w};
#pragma unroll
            for (int i = 0; i < 8; i++)
#pragma unroll
                for (int j = 0; j < 8; j++) acc[i][j] += ar[i] * wr[j];
        }
        if (more) {
            int ns = st ^ 1;
            As[ns][lk + 0][lr] = an.x; As[ns][lk + 1][lr] = an.y;
            As[ns][lk + 2][lr] = an.z; As[ns][lk + 3][lr] = an.w;
            Ws[ns][lk + 0][lr] = wn.x; Ws[ns][lk + 1][lr] = wn.y;
            Ws[ns][lk + 2][lr] = wn.z; Ws[ns][lk + 3][lr] = wn.w;
            __syncthreads();
            st = ns;
        }
    }

    float bb[8];
#pragma unroll
    for (int j = 0; j < 8; j++) {
        int n = n0 + (j < 4 ? tx * 4 + j : 64 + tx * 4 + (j - 4));
        float v = b1 ? b1[n] : 0.0f;
        if (b2) v += b2[n];
        bb[j] = v;
    }
#pragma unroll
    for (int i = 0; i < 8; i++) {
        int m = m0 + (i < 4 ? ty * 4 + i : 64 + ty * 4 + (i - 4));
        size_t row = (size_t)m * N;
        float4 o0, o1;
        o0.x = acc[i][0] + bb[0]; o0.y = acc[i][1] + bb[1];
        o0.z = acc[i][2] + bb[2]; o0.w = acc[i][3] + bb[3];
        o1.x = acc[i][4] + bb[4]; o1.y = acc[i][5] + bb[5];
        o1.z = acc[i][6] + bb[6]; o1.w = acc[i][7] + bb[7];
        *(float4*)&C[row + n0 + tx * 4]      = o0;
        *(float4*)&C[row + n0 + 64 + tx * 4] = o1;
    }
}

// ====== batched scores v2: S = scale * Q K^T, causal mask, double-buffered ====
__global__ __launch_bounds__(256) void gemm_tn_scores(
    const float* __restrict__ Qm, const float* __restrict__ Km,
    float* __restrict__ C, float scale)
{
    __shared__ float As[2][8][132];
    __shared__ float Ws[2][8][132];
    const size_t bo = (size_t)blockIdx.z * 262144;
    const float* A = Qm + bo;
    const float* W = Km + bo;
    float* Cb = C + bo;
    const int m0 = blockIdx.y * 128, n0 = blockIdx.x * 128;
    const int t = threadIdx.x;
    const int tx = t & 15, ty = t >> 4;
    const int lr = t >> 1, lk = (t & 1) * 4;

    float acc[8][8];
#pragma unroll
    for (int i = 0; i < 8; i++)
#pragma unroll
        for (int j = 0; j < 8; j++) acc[i][j] = 0.0f;

    const float* Ap = A + (size_t)(m0 + lr) * 512 + lk;
    const float* Wp = W + (size_t)(n0 + lr) * 512 + lk;

    {
        float4 a4 = *(const float4*)(Ap);
        float4 w4 = *(const float4*)(Wp);
        As[0][lk + 0][lr] = a4.x; As[0][lk + 1][lr] = a4.y;
        As[0][lk + 2][lr] = a4.z; As[0][lk + 3][lr] = a4.w;
        Ws[0][lk + 0][lr] = w4.x; Ws[0][lk + 1][lr] = w4.y;
        Ws[0][lk + 2][lr] = w4.z; Ws[0][lk + 3][lr] = w4.w;
    }
    __syncthreads();

    int st = 0;
    for (int k0 = 0; k0 < 512; k0 += 8) {
        float4 an, wn;
        const bool more = (k0 + 8) < 512;
        if (more) {
            an = *(const float4*)(Ap + k0 + 8);
            wn = *(const float4*)(Wp + k0 + 8);
        }
#pragma unroll
        for (int k = 0; k < 8; k++) {
            float4 A0 = *(const float4*)&As[st][k][ty * 4];
            float4 A1 = *(const float4*)&As[st][k][64 + ty * 4];
            float4 W0 = *(const float4*)&Ws[st][k][tx * 4];
            float4 W1 = *(const float4*)&Ws[st][k][64 + tx * 4];
            float ar[8] = {A0.x, A0.y, A0.z, A0.w, A1.x, A1.y, A1.z, A1.w};
            float wr[8] = {W0.x, W0.y, W0.z, W0.w, W1.x, W1.y, W1.z, W1.w};
#pragma unroll
            for (int i = 0; i < 8; i++)
#pragma unroll
                for (int j = 0; j < 8; j++) acc[i][j] += ar[i] * wr[j];
        }
        if (more) {
            int ns = st ^ 1;
            As[ns][lk + 0][lr] = an.x; As[ns][lk + 1][lr] = an.y;
            As[ns][lk + 2][lr] = an.z; As[ns][lk + 3][lr] = an.w;
            Ws[ns][lk + 0][lr] = wn.x; Ws[ns][lk + 1][lr] = wn.y;
            Ws[ns][lk + 2][lr] = wn.z; Ws[ns][lk + 3][lr] = wn.w;
            __syncthreads();
            st = ns;
        }
    }
#pragma unroll
    for (int i = 0; i < 8; i++) {
        int q = m0 + (i < 4 ? ty * 4 + i : 64 + ty * 4 + (i - 4));
#pragma unroll
        for (int j = 0; j < 8; j++) {
            int kk = n0 + (j < 4 ? tx * 4 + j : 64 + tx * 4 + (j - 4));
            float v = acc[i][j] * scale;
            if (kk > q) v = -1e30f;
            Cb[(size_t)q * 512 + kk] = v;
        }
    }
}

// ====== batched NN GEMM v2: O = attn @ V, double-buffered =====================
__global__ __launch_bounds__(256) void gemm_nn_b(
    const float* __restrict__ Am, const float* __restrict__ Bm, float* __restrict__ C)
{
    __shared__ float As[2][8][132];
    __shared__ float Bs[2][8][128];
    const size_t bo = (size_t)blockIdx.z * 262144;
    const float* A = Am + bo;
    const float* B = Bm + bo;
    float* Cb = C + bo;
    const int m0 = blockIdx.y * 128, n0 = blockIdx.x * 128;
    const int t = threadIdx.x;
    const int tx = t & 15, ty = t >> 4;
    const int lr = t >> 1, lk = (t & 1) * 4;
    const int kr = t >> 5, nq = t & 31;

    float acc[8][8];
#pragma unroll
    for (int i = 0; i < 8; i++)
#pragma unroll
        for (int j = 0; j < 8; j++) acc[i][j] = 0.0f;

    const float* Ap = A + (size_t)(m0 + lr) * 512 + lk;

    {
        float4 a4 = *(const float4*)(Ap);
        float4 b4 = *(const float4*)(B + (size_t)kr * 512 + n0 + nq * 4);
        As[0][lk + 0][lr] = a4.x; As[0][lk + 1][lr] = a4.y;
        As[0][lk + 2][lr] = a4.z; As[0][lk + 3][lr] = a4.w;
        *(float4*)&Bs[0][kr][nq * 4] = b4;
    }
    __syncthreads();

    int st = 0;
    for (int k0 = 0; k0 < 512; k0 += 8) {
        float4 an, bn;
        const bool more = (k0 + 8) < 512;
        if (more) {
            an = *(const float4*)(Ap + k0 + 8);
            bn = *(const float4*)(B + (size_t)(k0 + 8 + kr) * 512 + n0 + nq * 4);
        }
#pragma unroll
        for (int k = 0; k < 8; k++) {
            float4 A0 = *(const float4*)&As[st][k][ty * 4];
            float4 A1 = *(const float4*)&As[st][k][64 + ty * 4];
            float4 W0 = *(const float4*)&Bs[st][k][tx * 4];
            float4 W1 = *(const float4*)&Bs[st][k][64 + tx * 4];
            float ar[8] = {A0.x, A0.y, A0.z, A0.w, A1.x, A1.y, A1.z, A1.w};
            float wr[8] = {W0.x, W0.y, W0.z, W0.w, W1.x, W1.y, W1.z, W1.w};
#pragma unroll
            for (int i = 0; i < 8; i++)
#pragma unroll
                for (int j = 0; j < 8; j++) acc[i][j] += ar[i] * wr[j];
        }
        if (more) {
            int ns = st ^ 1;
            As[ns][lk + 0][lr] = an.x; As[ns][lk + 1][lr] = an.y;
            As[ns][lk + 2][lr] = an.z; As[ns][lk + 3][lr] = an.w;
            *(float4*)&Bs[ns][kr][nq * 4] = bn;
            __syncthreads();
            st = ns;
        }
    }
#pragma unroll
    for (int i = 0; i < 8; i++) {
        int m = m0 + (i < 4 ? ty * 4 + i : 64 + ty * 4 + (i - 4));
        size_t row = (size_t)m * 512;
        float4 o0, o1;
        o0.x = acc[i][0]; o0.y = acc[i][1]; o0.z = acc[i][2]; o0.w = acc[i][3];
        o1.x = acc[i][4]; o1.y = acc[i][5]; o1.z = acc[i][6]; o1.w = acc[i][7];
        *(float4*)&Cb[row + n0 + tx * 4]      = o0;
        *(float4*)&Cb[row + n0 + 64 + tx * 4] = o1;
    }
}

// ======================= copy observed rows into lstm_hidden ==================
__global__ void copy_obs_k(const float* __restrict__ obs, float* __restrict__ LH)
{
    size_t i = (size_t)blockIdx.x * blockDim.x + threadIdx.x;
    if (i < (size_t)Bn * OBSn * Hd) {
        size_t b = i >> 17;
        size_t rem = i & 131071;
        LH[b * 262144 + rem] = obs[i];
    }
}

// ============ persistent LSTM v4: coalesced h-copy ============================
#define HSTRIDE 516
#define WSTRIDE 512
__global__ __launch_bounds__(256, 1) void lstm_persist(
    const float* __restrict__ obs, const float* __restrict__ XG,
    const float* __restrict__ Whh, float* __restrict__ LH)
{
    extern __shared__ float sh[];
    float* Hs = sh;                        // 64 x HSTRIDE
    float* Ws = sh + 64 * HSTRIDE;         // 16 x WSTRIDE
    __shared__ float gsm[4 * 64 * 4];

    const int t = threadIdx.x;
    const int ublk = blockIdx.x * 4;
    const unsigned nb = gridDim.x;

    for (int idx = t; idx < 16 * 128; idx += 256) {
        int row = idx >> 7, q = idx & 127;
        int g = row >> 2, j = row & 3;
        float4 v = *(const float4*)(Whh + (size_t)(g * 512 + ublk + j) * 512 + q * 4);
        *(float4*)(Ws + row * WSTRIDE + q * 4) = v;
    }

    const int wid = t >> 5, lane = t & 31;
    const int g = wid >> 1, bh = wid & 1;
    const int batch = bh * 32 + lane;

    const int pb = t >> 2, pj = t & 3;
    float c_reg = obs[(size_t)pb * 131072 + 255 * 512 + ublk + pj];

    // coalesced copy role: 2 rows per iter, thread covers float4 at (crow, ccol)
    const int crow = t >> 7;            // 0/1
    const int ccol = (t & 127) * 4;     // 0..508

    for (int s = 0; s < 256; s++) {
        const float* xrow = XG + (size_t)(pb * 256 + s) * 2048 + ublk + pj;
        float xg0 = __ldcg(xrow);
        float xg1 = __ldcg(xrow + 512);
        float xg2 = __ldcg(xrow + 1024);
        float xg3 = __ldcg(xrow + 1536);

        {
            const float* hsrc; size_t hstr;
            if (s == 0) { hsrc = obs + 255 * 512; hstr = 131072; }
            else        { hsrc = LH + (size_t)(255 + s) * 512; hstr = 262144; }
#pragma unroll
            for (int i = 0; i < 32; i++) {
                int r = 2 * i + crow;
                float4 v = __ldcg((const float4*)(hsrc + (size_t)r * hstr + ccol));
                *(float4*)(Hs + r * HSTRIDE + ccol) = v;
            }
        }
        __syncthreads();

        {
            const float* xp = Hs + batch * HSTRIDE;
            const float* wp = Ws + (g * 4) * WSTRIDE;
            float a0 = 0.f, a1 = 0.f, a2 = 0.f, a3 = 0.f;
#pragma unroll 8
            for (int k0 = 0; k0 < 512; k0 += 4) {
                float4 xv = *(const float4*)(xp + k0);
                float4 w0 = *(const float4*)(wp + k0);
                float4 w1 = *(const float4*)(wp + WSTRIDE + k0);
                float4 w2 = *(const float4*)(wp + 2 * WSTRIDE + k0);
                float4 w3 = *(const float4*)(wp + 3 * WSTRIDE + k0);
                a0 += xv.x * w0.x + xv.y * w0.y + xv.z * w0.z + xv.w * w0.w;
                a1 += xv.x * w1.x + xv.y * w1.y + xv.z * w1.z + xv.w * w1.w;
                a2 += xv.x * w2.x + xv.y * w2.y + xv.z * w2.z + xv.w * w2.w;
                a3 += xv.x * w3.x + xv.y * w3.y + xv.z * w3.z + xv.w * w3.w;
            }
            float4 o; o.x = a0; o.y = a1; o.z = a2; o.w = a3;
            *(float4*)(gsm + (g * 64 + batch) * 4) = o;
        }
        __syncthreads();

        {
            float gi = gsm[(0 * 64 + pb) * 4 + pj] + xg0;
            float gf = gsm[(1 * 64 + pb) * 4 + pj] + xg1;
            float gg = gsm[(2 * 64 + pb) * 4 + pj] + xg2;
            float go = gsm[(3 * 64 + pb) * 4 + pj] + xg3;
            c_reg = sigmoidf_(gf) * c_reg + sigmoidf_(gi) * tanhf(gg);
            float hv = sigmoidf_(go) * tanhf(c_reg);
            LH[(size_t)pb * 262144 + (size_t)(256 + s) * 512 + ublk + pj] = hv;
        }

        __threadfence();
        __syncthreads();
        if (t == 0) {
            unsigned snap = g_bar_gen;
            unsigned old = atomicAdd(&g_bar_cnt, 1u);
            if (old == nb - 1u) {
                g_bar_cnt = 0;
                __threadfence();
                g_bar_gen = snap + 1u;
            } else {
                while (g_bar_gen == snap) __nanosleep(32);
            }
            __threadfence();
        }
        __syncthreads();
    }
}

// ====================== fused GLU + LayerNorm (one block/row) =================
__global__ __launch_bounds__(256) void gluln_k(
    const float* __restrict__ a1, const float* __restrict__ a2,
    const float* __restrict__ y1, const float* __restrict__ y2,
    const float* __restrict__ gamma, const float* __restrict__ beta,
    float* __restrict__ outp, int splitY)
{
    __shared__ float red[8];
    const int r = blockIdx.x;
    const int t = threadIdx.x;
    const float* yp;
    if (splitY) {
        int b = r >> 9, tt = r & 511;
        yp = (tt < 256) ? (y1 + ((size_t)(b * 256 + tt)) * 512)
                        : (y2 + ((size_t)(b * 256 + tt - 256)) * 512);
    } else {
        yp = y1 + (size_t)r * 512;
    }
    const float* p1 = a1 + (size_t)r * 512;
    const float* p2 = a2 + (size_t)r * 512;
    float z0 = sigmoidf_(p1[t])       * p2[t]       + yp[t];
    float z1 = sigmoidf_(p1[t + 256]) * p2[t + 256] + yp[t + 256];

    float s = z0 + z1;
#pragma unroll
    for (int o = 16; o > 0; o >>= 1) s += __shfl_xor_sync(0xffffffffu, s, o);
    if ((t & 31) == 0) red[t >> 5] = s;
    __syncthreads();
    if (t < 32) {
        float a = (t < 8) ? red[t] : 0.0f;
#pragma unroll
        for (int o = 4; o > 0; o >>= 1) a += __shfl_xor_sync(0xffffffffu, a, o);
        if (t == 0) red[0] = a;
    }
    __syncthreads();
    float mu = red[0] * (1.0f / 512.0f);
    float d0 = z0 - mu, d1 = z1 - mu;
    float s2 = d0 * d0 + d1 * d1;
    __syncthreads();
#pragma unroll
    for (int o = 16; o > 0; o >>= 1) s2 += __shfl_xor_sync(0xffffffffu, s2, o);
    if ((t & 31) == 0) red[t >> 5] = s2;
    __syncthreads();
    if (t < 32) {
        float a = (t < 8) ? red[t] : 0.0f;
#pragma unroll
        for (int o = 4; o > 0; o >>= 1) a += __shfl_xor_sync(0xffffffffu, a, o);
        if (t == 0) red[0] = a;
    }
    __syncthreads();
    float inv = rsqrtf(red[0] * (1.0f / 512.0f) + 1e-5f);
    outp[(size_t)r * 512 + t]       = gamma[t]       * d0 * inv + beta[t];
    outp[(size_t)r * 512 + t + 256] = gamma[t + 256] * d1 * inv + beta[t + 256];
}

// ========================= row softmax over 512 cols ==========================
__global__ __launch_bounds__(256) void softmax_k(
    const float* __restrict__ S, float* __restrict__ A)
{
    __shared__ float red[8];
    const int r = blockIdx.x;
    const int t = threadIdx.x;
    const float* p = S + (size_t)r * 512;
    float v0 = p[t], v1 = p[t + 256];
    float m = fmaxf(v0, v1);
#pragma unroll
    for (int o = 16; o > 0; o >>= 1) m = fmaxf(m, __shfl_xor_sync(0xffffffffu, m, o));
    if ((t & 31) == 0) red[t >> 5] = m;
    __syncthreads();
    if (t < 32) {
        float a = (t < 8) ? red[t] : -3.4e38f;
#pragma unroll
        for (int o = 4; o > 0; o >>= 1) a = fmaxf(a, __shfl_xor_sync(0xffffffffu, a, o));
        if (t == 0) red[0] = a;
    }
    __syncthreads();
    float mx = red[0];
    float e0 = expf(v0 - mx), e1 = expf(v1 - mx);
    float s = e0 + e1;
    __syncthreads();
#pragma unroll
    for (int o = 16; o > 0; o >>= 1) s += __shfl_xor_sync(0xffffffffu, s, o);
    if ((t & 31) == 0) red[t >> 5] = s;
    __syncthreads();
    if (t < 32) {
        float a = (t < 8) ? red[t] : 0.0f;
#pragma unroll
        for (int o = 4; o > 0; o >>= 1) a += __shfl_xor_sync(0xffffffffu, a, o);
        if (t == 0) red[0] = a;
    }
    __syncthreads();
    float inv = 1.0f / red[0];
    A[(size_t)r * 512 + t]       = e0 * inv;
    A[(size_t)r * 512 + t + 256] = e1 * inv;
}

// ================================= host =======================================
extern "C" void kernel_launch(void* const* d_in, const int* in_sizes, int n_in,
                              void* d_out, int out_size)
{
    const float* obs   = (const float*)d_in[0];
    const float* fut   = (const float*)d_in[1];
    const float* W_ih  = (const float*)d_in[2];
    const float* W_hh  = (const float*)d_in[3];
    const float* b_ih  = (const float*)d_in[4];
    const float* b_hh  = (const float*)d_in[5];
    const float* g1W1  = (const float*)d_in[6];
    const float* g1b1  = (const float*)d_in[7];
    const float* g1W2  = (const float*)d_in[8];
    const float* g1b2  = (const float*)d_in[9];
    const float* g1g   = (const float*)d_in[10];
    const float* g1b   = (const float*)d_in[11];
    const float* Wq    = (const float*)d_in[12];
    const float* bq    = (const float*)d_in[13];
    const float* Wk    = (const float*)d_in[14];
    const float* bk    = (const float*)d_in[15];
    const float* Wv    = (const float*)d_in[16];
    const float* bv    = (const float*)d_in[17];
    const float* Wo    = (const float*)d_in[18];
    const float* bo    = (const float*)d_in[19];
    const float* g2W1  = (const float*)d_in[20];
    const float* g2b1  = (const float*)d_in[21];
    const float* g2W2  = (const float*)d_in[22];
    const float* g2b2  = (const float*)d_in[23];
    const float* g2g   = (const float*)d_in[24];
    const float* g2b   = (const float*)d_in[25];

    float* out       = (float*)d_out;
    float* glu_delta = out;
    float* glu_phi   = out + (size_t)OUT1;
    float* attn      = out + (size_t)2 * OUT1;

    float *XG, *LH, *A1, *A2, *Qb, *Kb, *Vb;
    cudaGetSymbolAddress((void**)&XG, d_XG);
    cudaGetSymbolAddress((void**)&LH, d_LH);
    cudaGetSymbolAddress((void**)&A1, d_A1);
    cudaGetSymbolAddress((void**)&A2, d_A2);
    cudaGetSymbolAddress((void**)&Qb, d_Qb);
    cudaGetSymbolAddress((void**)&Kb, d_Kb);
    cudaGetSymbolAddress((void**)&Vb, d_Vb);

    // 1. X_gates = fut @ W_ih^T + (b_ih + b_hh)
    gemm_tn<<<dim3(G4 / 128, BF / 128), 256>>>(fut, W_ih, b_ih, b_hh, XG, BF, G4, Hd);

    // 2. lstm_hidden[:, :256, :] = vsn_observed
    copy_obs_k<<<(Bn * OBSn * Hd + 255) / 256, 256>>>(obs, LH);

    // 3. persistent LSTM over all 256 steps
    {
        const int smem = (64 * HSTRIDE + 16 * WSTRIDE) * 4;   // 164864 bytes
        cudaFuncSetAttribute(lstm_persist, cudaFuncAttributeMaxDynamicSharedMemorySize, smem);
        lstm_persist<<<128, 256, smem>>>(obs, XG, W_hh, LH);
    }

    // 4. GLU-LN #1 -> glu_phi
    gemm_tn<<<dim3(4, 256), 256>>>(LH, g1W1, g1b1, nullptr, A1, BT, Hd, Hd);
    gemm_tn<<<dim3(4, 256), 256>>>(LH, g1W2, g1b2, nullptr, A2, BT, Hd, Hd);
    gluln_k<<<BT, 256>>>(A1, A2, obs, fut, g1g, g1b, glu_phi, 1);

    // 5. QKV
    gemm_tn<<<dim3(4, 256), 256>>>(glu_phi, Wq, bq, nullptr, Qb, BT, Hd, Hd);
    gemm_tn<<<dim3(4, 256), 256>>>(glu_phi, Wk, bk, nullptr, Kb, BT, Hd, Hd);
    gemm_tn<<<dim3(4, 256), 256>>>(glu_phi, Wv, bv, nullptr, Vb, BT, Hd, Hd);

    // 6. scores (reuse XG) + softmax -> attn
    gemm_tn_scores<<<dim3(4, 4, 64), 256>>>(Qb, Kb, XG, 0.04419417382415922f);
    softmax_k<<<BT, 256>>>(XG, attn);

    // 7. attn @ V -> reuse Qb; projection -> reuse Kb
    gemm_nn_b<<<dim3(4, 4, 64), 256>>>(attn, Vb, Qb);
    gemm_tn<<<dim3(4, 256), 256>>>(Qb, Wo, bo, nullptr, Kb, BT, Hd, Hd);

    // 8. GLU-LN #2 -> glu_delta
    gemm_tn<<<dim3(4, 256), 256>>>(Kb, g2W1, g2b1, nullptr, A1, BT, Hd, Hd);
    gemm_tn<<<dim3(4, 256), 256>>>(Kb, g2W2, g2b2, nullptr, A2, BT, Hd, Hd);
    gluln_k<<<BT, 256>>>(A1, A2, glu_phi, nullptr, g2g, g2b, glu_delta, 0);
}

// round 8
// speedup vs baseline: 2.3132x; 1.2535x over previous
#include <cuda_runtime.h>
#include <cstdint>
#include <cstddef>

// Problem dims
#define Hd    512
#define Bn    64
#define OBSn  256
#define FUTn  256
#define Tn    512
#define G4    2048
#define BT    32768
#define BF    16384
#define OUT1  16777216

// ---------------- scratch --------------------------------------------------
__device__ float d_XG[(size_t)BF * G4];
__device__ float d_LH[(size_t)BT * Hd];
__device__ float d_A1[(size_t)BT * Hd];
__device__ float d_A2[(size_t)BT * Hd];
__device__ float d_Qb[(size_t)BT * Hd];
__device__ float d_Kb[(size_t)BT * Hd];
__device__ float d_Vb[(size_t)BT * Hd];

__device__ unsigned g_bar_cnt = 0;
__device__ volatile unsigned g_bar_gen = 0;

__device__ __forceinline__ float sigmoidf_(float x) { return 1.0f / (1.0f + expf(-x)); }

// ---------------- mma.sync tf32 helpers (sm_80+ PTX, valid on sm_103) -------
__device__ __forceinline__ uint32_t f2tf32(float x) {
    uint32_t r;
    asm("cvt.rna.tf32.f32 %0, %1;" : "=r"(r) : "f"(x));
    return r;
}
__device__ __forceinline__ void mma_tf32(float* c, const uint32_t* a, const uint32_t* b) {
    asm volatile(
        "mma.sync.aligned.m16n8k8.row.col.f32.tf32.tf32.f32 "
        "{%0,%1,%2,%3}, {%4,%5,%6,%7}, {%8,%9}, {%0,%1,%2,%3};"
        : "+f"(c[0]), "+f"(c[1]), "+f"(c[2]), "+f"(c[3])
        : "r"(a[0]), "r"(a[1]), "r"(a[2]), "r"(a[3]), "r"(b[0]), "r"(b[1]));
}

// =========== tf32 mma TN GEMM: C = A[M,K] @ W[N,K]^T + b1 + b2 ===============
// 128x128 tile, BK=16, 256 thr (8 warps 2x4), warp tile 64x32 (4x4 m16n8 mmas).
// SMEM [k][row] stride 132: fragment LDS bank = (4q+g+const)%32 -> conflict-free.
__global__ __launch_bounds__(256) void gemm_mma(
    const float* __restrict__ A, const float* __restrict__ W,
    const float* __restrict__ b1, const float* __restrict__ b2,
    float* __restrict__ C, int M, int N, int K)
{
    __shared__ float As[2][16][132];
    __shared__ float Ws[2][16][132];
    __shared__ float bias_s[128];

    const int t = threadIdx.x, wid = t >> 5, lane = t & 31;
    const int m0 = blockIdx.y * 128, n0 = blockIdx.x * 128;
    const int wm = (wid >> 2) * 64, wn = (wid & 3) * 32;
    const int g = lane >> 2, q = lane & 3;

    if (t < 128) {
        float v = b1 ? b1[n0 + t] : 0.0f;
        if (b2) v += b2[n0 + t];
        bias_s[t] = v;
    }

    float c[4][4][4];
#pragma unroll
    for (int mt = 0; mt < 4; mt++)
#pragma unroll
        for (int nt = 0; nt < 4; nt++)
#pragma unroll
            for (int i = 0; i < 4; i++) c[mt][nt][i] = 0.0f;

    const int lr = t >> 1, lk = (t & 1) * 8;
    const float* Ap = A + (size_t)(m0 + lr) * K + lk;
    const float* Wp = W + (size_t)(n0 + lr) * K + lk;

    {   // prologue: stage 0 (k 0..15)
        float4 a0 = *(const float4*)(Ap);
        float4 a1 = *(const float4*)(Ap + 4);
        float4 w0 = *(const float4*)(Wp);
        float4 w1 = *(const float4*)(Wp + 4);
        As[0][lk + 0][lr] = a0.x; As[0][lk + 1][lr] = a0.y;
        As[0][lk + 2][lr] = a0.z; As[0][lk + 3][lr] = a0.w;
        As[0][lk + 4][lr] = a1.x; As[0][lk + 5][lr] = a1.y;
        As[0][lk + 6][lr] = a1.z; As[0][lk + 7][lr] = a1.w;
        Ws[0][lk + 0][lr] = w0.x; Ws[0][lk + 1][lr] = w0.y;
        Ws[0][lk + 2][lr] = w0.z; Ws[0][lk + 3][lr] = w0.w;
        Ws[0][lk + 4][lr] = w1.x; Ws[0][lk + 5][lr] = w1.y;
        Ws[0][lk + 6][lr] = w1.z; Ws[0][lk + 7][lr] = w1.w;
    }
    __syncthreads();

    int st = 0;
    for (int k0 = 0; k0 < K; k0 += 16) {
        float4 na0, na1, nw0, nw1;
        const bool more = (k0 + 16) < K;
        if (more) {
            na0 = *(const float4*)(Ap + k0 + 16);
            na1 = *(const float4*)(Ap + k0 + 20);
            nw0 = *(const float4*)(Wp + k0 + 16);
            nw1 = *(const float4*)(Wp + k0 + 20);
        }
#pragma unroll
        for (int s = 0; s < 2; s++) {
            const int kb = s * 8;
            uint32_t af[4][4], bf[4][2];
#pragma unroll
            for (int mt = 0; mt < 4; mt++) {
                int mr = wm + mt * 16 + g;
                af[mt][0] = f2tf32(As[st][kb + q][mr]);
                af[mt][1] = f2tf32(As[st][kb + q][mr + 8]);
                af[mt][2] = f2tf32(As[st][kb + q + 4][mr]);
                af[mt][3] = f2tf32(As[st][kb + q + 4][mr + 8]);
            }
#pragma unroll
            for (int nt = 0; nt < 4; nt++) {
                int nc = wn + nt * 8 + g;
                bf[nt][0] = f2tf32(Ws[st][kb + q][nc]);
                bf[nt][1] = f2tf32(Ws[st][kb + q + 4][nc]);
            }
#pragma unroll
            for (int mt = 0; mt < 4; mt++)
#pragma unroll
                for (int nt = 0; nt < 4; nt++)
                    mma_tf32(c[mt][nt], af[mt], bf[nt]);
        }
        if (more) {
            int ns = st ^ 1;
            As[ns][lk + 0][lr] = na0.x; As[ns][lk + 1][lr] = na0.y;
            As[ns][lk + 2][lr] = na0.z; As[ns][lk + 3][lr] = na0.w;
            As[ns][lk + 4][lr] = na1.x; As[ns][lk + 5][lr] = na1.y;
            As[ns][lk + 6][lr] = na1.z; As[ns][lk + 7][lr] = na1.w;
            Ws[ns][lk + 0][lr] = nw0.x; Ws[ns][lk + 1][lr] = nw0.y;
            Ws[ns][lk + 2][lr] = nw0.z; Ws[ns][lk + 3][lr] = nw0.w;
            Ws[ns][lk + 4][lr] = nw1.x; Ws[ns][lk + 5][lr] = nw1.y;
            Ws[ns][lk + 6][lr] = nw1.z; Ws[ns][lk + 7][lr] = nw1.w;
            __syncthreads();
            st = ns;
        }
    }

    // epilogue: c0/c1 at (row g, col 2q/2q+1), c2/c3 at row g+8
#pragma unroll
    for (int mt = 0; mt < 4; mt++) {
        int mrow = m0 + wm + mt * 16 + g;
#pragma unroll
        for (int nt = 0; nt < 4; nt++) {
            int ncol = wn + nt * 8 + 2 * q;           // col within 128-tile
            float b0v = bias_s[ncol], b1v = bias_s[ncol + 1];
            float2 o0 = make_float2(c[mt][nt][0] + b0v, c[mt][nt][1] + b1v);
            float2 o1 = make_float2(c[mt][nt][2] + b0v, c[mt][nt][3] + b1v);
            *(float2*)&C[(size_t)mrow * N + n0 + ncol]       = o0;
            *(float2*)&C[(size_t)(mrow + 8) * N + n0 + ncol] = o1;
        }
    }
}

// ====== batched scores: S = scale*Q K^T, causal, triangle-skip (FFMA) ========
__global__ __launch_bounds__(256) void gemm_tn_scores(
    const float* __restrict__ Qm, const float* __restrict__ Km,
    float* __restrict__ C, float scale)
{
    __shared__ float As[2][8][132];
    __shared__ float Ws[2][8][132];
    const size_t bo = (size_t)blockIdx.z * 262144;
    const int m0 = blockIdx.y * 128, n0 = blockIdx.x * 128;
    float* Cb = C + bo;
    const int t = threadIdx.x;

    if (n0 > m0 + 127) {   // fully masked tile
        float4 neg = make_float4(-1e30f, -1e30f, -1e30f, -1e30f);
        for (int idx = t; idx < 4096; idx += 256) {
            int r = idx >> 5, c4 = idx & 31;
            *(float4*)&Cb[(size_t)(m0 + r) * 512 + n0 + c4 * 4] = neg;
        }
        return;
    }

    const float* A = Qm + bo;
    const float* W = Km + bo;
    const int tx = t & 15, ty = t >> 4;
    const int lr = t >> 1, lk = (t & 1) * 4;

    float acc[8][8];
#pragma unroll
    for (int i = 0; i < 8; i++)
#pragma unroll
        for (int j = 0; j < 8; j++) acc[i][j] = 0.0f;

    const float* Ap = A + (size_t)(m0 + lr) * 512 + lk;
    const float* Wp = W + (size_t)(n0 + lr) * 512 + lk;

    {
        float4 a4 = *(const float4*)(Ap);
        float4 w4 = *(const float4*)(Wp);
        As[0][lk + 0][lr] = a4.x; As[0][lk + 1][lr] = a4.y;
        As[0][lk + 2][lr] = a4.z; As[0][lk + 3][lr] = a4.w;
        Ws[0][lk + 0][lr] = w4.x; Ws[0][lk + 1][lr] = w4.y;
        Ws[0][lk + 2][lr] = w4.z; Ws[0][lk + 3][lr] = w4.w;
    }
    __syncthreads();

    int st = 0;
    for (int k0 = 0; k0 < 512; k0 += 8) {
        float4 an, wn;
        const bool more = (k0 + 8) < 512;
        if (more) {
            an = *(const float4*)(Ap + k0 + 8);
            wn = *(const float4*)(Wp + k0 + 8);
        }
#pragma unroll
        for (int k = 0; k < 8; k++) {
            float4 A0 = *(const float4*)&As[st][k][ty * 4];
            float4 A1 = *(const float4*)&As[st][k][64 + ty * 4];
            float4 W0 = *(const float4*)&Ws[st][k][tx * 4];
            float4 W1 = *(const float4*)&Ws[st][k][64 + tx * 4];
            float ar[8] = {A0.x, A0.y, A0.z, A0.w, A1.x, A1.y, A1.z, A1.w};
            float wr[8] = {W0.x, W0.y, W0.z, W0.w, W1.x, W1.y, W1.z, W1.w};
#pragma unroll
            for (int i = 0; i < 8; i++)
#pragma unroll
                for (int j = 0; j < 8; j++) acc[i][j] += ar[i] * wr[j];
        }
        if (more) {
            int ns = st ^ 1;
            As[ns][lk + 0][lr] = an.x; As[ns][lk + 1][lr] = an.y;
            As[ns][lk + 2][lr] = an.z; As[ns][lk + 3][lr] = an.w;
            Ws[ns][lk + 0][lr] = wn.x; Ws[ns][lk + 1][lr] = wn.y;
            Ws[ns][lk + 2][lr] = wn.z; Ws[ns][lk + 3][lr] = wn.w;
            __syncthreads();
            st = ns;
        }
    }
#pragma unroll
    for (int i = 0; i < 8; i++) {
        int qn = m0 + (i < 4 ? ty * 4 + i : 64 + ty * 4 + (i - 4));
#pragma unroll
        for (int j = 0; j < 8; j++) {
            int kk = n0 + (j < 4 ? tx * 4 + j : 64 + tx * 4 + (j - 4));
            float v = acc[i][j] * scale;
            if (kk > qn) v = -1e30f;
            Cb[(size_t)qn * 512 + kk] = v;
        }
    }
}

// ====== batched NN GEMM: O = attn @ V, K truncated to causal extent ==========
__global__ __launch_bounds__(256) void gemm_nn_b(
    const float* __restrict__ Am, const float* __restrict__ Bm, float* __restrict__ C)
{
    __shared__ float As[2][8][132];
    __shared__ float Bs[2][8][128];
    const size_t bo = (size_t)blockIdx.z * 262144;
    const float* A = Am + bo;
    const float* B = Bm + bo;
    float* Cb = C + bo;
    const int m0 = blockIdx.y * 128, n0 = blockIdx.x * 128;
    const int Kmax = m0 + 128;             // attn[q,k]=0 for k>q (exact)
    const int t = threadIdx.x;
    const int tx = t & 15, ty = t >> 4;
    const int lr = t >> 1, lk = (t & 1) * 4;
    const int kr = t >> 5, nq = t & 31;

    float acc[8][8];
#pragma unroll
    for (int i = 0; i < 8; i++)
#pragma unroll
        for (int j = 0; j < 8; j++) acc[i][j] = 0.0f;

    const float* Ap = A + (size_t)(m0 + lr) * 512 + lk;

    {
        float4 a4 = *(const float4*)(Ap);
        float4 b4 = *(const float4*)(B + (size_t)kr * 512 + n0 + nq * 4);
        As[0][lk + 0][lr] = a4.x; As[0][lk + 1][lr] = a4.y;
        As[0][lk + 2][lr] = a4.z; As[0][lk + 3][lr] = a4.w;
        *(float4*)&Bs[0][kr][nq * 4] = b4;
    }
    __syncthreads();

    int st = 0;
    for (int k0 = 0; k0 < Kmax; k0 += 8) {
        float4 an, bn;
        const bool more = (k0 + 8) < Kmax;
        if (more) {
            an = *(const float4*)(Ap + k0 + 8);
            bn = *(const float4*)(B + (size_t)(k0 + 8 + kr) * 512 + n0 + nq * 4);
        }
#pragma unroll
        for (int k = 0; k < 8; k++) {
            float4 A0 = *(const float4*)&As[st][k][ty * 4];
            float4 A1 = *(const float4*)&As[st][k][64 + ty * 4];
            float4 W0 = *(const float4*)&Bs[st][k][tx * 4];
            float4 W1 = *(const float4*)&Bs[st][k][64 + tx * 4];
            float ar[8] = {A0.x, A0.y, A0.z, A0.w, A1.x, A1.y, A1.z, A1.w};
            float wr[8] = {W0.x, W0.y, W0.z, W0.w, W1.x, W1.y, W1.z, W1.w};
#pragma unroll
            for (int i = 0; i < 8; i++)
#pragma unroll
                for (int j = 0; j < 8; j++) acc[i][j] += ar[i] * wr[j];
        }
        if (more) {
            int ns = st ^ 1;
            As[ns][lk + 0][lr] = an.x; As[ns][lk + 1][lr] = an.y;
            As[ns][lk + 2][lr] = an.z; As[ns][lk + 3][lr] = an.w;
            *(float4*)&Bs[ns][kr][nq * 4] = bn;
            __syncthreads();
            st = ns;
        }
    }
#pragma unroll
    for (int i = 0; i < 8; i++) {
        int m = m0 + (i < 4 ? ty * 4 + i : 64 + ty * 4 + (i - 4));
        size_t row = (size_t)m * 512;
        float4 o0, o1;
        o0.x = acc[i][0]; o0.y = acc[i][1]; o0.z = acc[i][2]; o0.w = acc[i][3];
        o1.x = acc[i][4]; o1.y = acc[i][5]; o1.z = acc[i][6]; o1.w = acc[i][7];
        *(float4*)&Cb[row + n0 + tx * 4]      = o0;
        *(float4*)&Cb[row + n0 + 64 + tx * 4] = o1;
    }
}

// ======================= copy observed rows into lstm_hidden ==================
__global__ void copy_obs_k(const float* __restrict__ obs, float* __restrict__ LH)
{
    size_t i = (size_t)blockIdx.x * blockDim.x + threadIdx.x;
    if (i < (size_t)Bn * OBSn * Hd) {
        size_t b = i >> 17;
        size_t rem = i & 131071;
        LH[b * 262144 + rem] = obs[i];
    }
}

// ============ persistent LSTM (v4: passing) ===================================
#define HSTRIDE 516
#define WSTRIDE 512
__global__ __launch_bounds__(256, 1) void lstm_persist(
    const float* __restrict__ obs, const float* __restrict__ XG,
    const float* __restrict__ Whh, float* __restrict__ LH)
{
    extern __shared__ float sh[];
    float* Hs = sh;
    float* Ws = sh + 64 * HSTRIDE;
    __shared__ float gsm[4 * 64 * 4];

    const int t = threadIdx.x;
    const int ublk = blockIdx.x * 4;
    const unsigned nb = gridDim.x;

    for (int idx = t; idx < 16 * 128; idx += 256) {
        int row = idx >> 7, qq = idx & 127;
        int g = row >> 2, j = row & 3;
        float4 v = *(const float4*)(Whh + (size_t)(g * 512 + ublk + j) * 512 + qq * 4);
        *(float4*)(Ws + row * WSTRIDE + qq * 4) = v;
    }

    const int wid = t >> 5, lane = t & 31;
    const int g = wid >> 1, bh = wid & 1;
    const int batch = bh * 32 + lane;

    const int pb = t >> 2, pj = t & 3;
    float c_reg = obs[(size_t)pb * 131072 + 255 * 512 + ublk + pj];

    const int crow = t >> 7;
    const int ccol = (t & 127) * 4;

    for (int s = 0; s < 256; s++) {
        const float* xrow = XG + (size_t)(pb * 256 + s) * 2048 + ublk + pj;
        float xg0 = __ldcg(xrow);
        float xg1 = __ldcg(xrow + 512);
        float xg2 = __ldcg(xrow + 1024);
        float xg3 = __ldcg(xrow + 1536);

        {
            const float* hsrc; size_t hstr;
            if (s == 0) { hsrc = obs + 255 * 512; hstr = 131072; }
            else        { hsrc = LH + (size_t)(255 + s) * 512; hstr = 262144; }
#pragma unroll
            for (int i = 0; i < 32; i++) {
                int r = 2 * i + crow;
                float4 v = __ldcg((const float4*)(hsrc + (size_t)r * hstr + ccol));
                *(float4*)(Hs + r * HSTRIDE + ccol) = v;
            }
        }
        __syncthreads();

        {
            const float* xp = Hs + batch * HSTRIDE;
            const float* wp = Ws + (g * 4) * WSTRIDE;
            float a0 = 0.f, a1 = 0.f, a2 = 0.f, a3 = 0.f;
#pragma unroll 8
            for (int k0 = 0; k0 < 512; k0 += 4) {
                float4 xv = *(const float4*)(xp + k0);
                float4 w0 = *(const float4*)(wp + k0);
                float4 w1 = *(const float4*)(wp + WSTRIDE + k0);
                float4 w2 = *(const float4*)(wp + 2 * WSTRIDE + k0);
                float4 w3 = *(const float4*)(wp + 3 * WSTRIDE + k0);
                a0 += xv.x * w0.x + xv.y * w0.y + xv.z * w0.z + xv.w * w0.w;
                a1 += xv.x * w1.x + xv.y * w1.y + xv.z * w1.z + xv.w * w1.w;
                a2 += xv.x * w2.x + xv.y * w2.y + xv.z * w2.z + xv.w * w2.w;
                a3 += xv.x * w3.x + xv.y * w3.y + xv.z * w3.z + xv.w * w3.w;
            }
            float4 o; o.x = a0; o.y = a1; o.z = a2; o.w = a3;
            *(float4*)(gsm + (g * 64 + batch) * 4) = o;
        }
        __syncthreads();

        {
            float gi = gsm[(0 * 64 + pb) * 4 + pj] + xg0;
            float gf = gsm[(1 * 64 + pb) * 4 + pj] + xg1;
            float gg = gsm[(2 * 64 + pb) * 4 + pj] + xg2;
            float go = gsm[(3 * 64 + pb) * 4 + pj] + xg3;
            c_reg = sigmoidf_(gf) * c_reg + sigmoidf_(gi) * tanhf(gg);
            float hv = sigmoidf_(go) * tanhf(c_reg);
            LH[(size_t)pb * 262144 + (size_t)(256 + s) * 512 + ublk + pj] = hv;
        }

        __threadfence();
        __syncthreads();
        if (t == 0) {
            unsigned snap = g_bar_gen;
            unsigned old = atomicAdd(&g_bar_cnt, 1u);
            if (old == nb - 1u) {
                g_bar_cnt = 0;
                __threadfence();
                g_bar_gen = snap + 1u;
            } else {
                while (g_bar_gen == snap) __nanosleep(32);
            }
            __threadfence();
        }
        __syncthreads();
    }
}

// ====================== fused GLU + LayerNorm =================================
__global__ __launch_bounds__(256) void gluln_k(
    const float* __restrict__ a1, const float* __restrict__ a2,
    const float* __restrict__ y1, const float* __restrict__ y2,
    const float* __restrict__ gamma, const float* __restrict__ beta,
    float* __restrict__ outp, int splitY)
{
    __shared__ float red[8];
    const int r = blockIdx.x;
    const int t = threadIdx.x;
    const float* yp;
    if (splitY) {
        int b = r >> 9, tt = r & 511;
        yp = (tt < 256) ? (y1 + ((size_t)(b * 256 + tt)) * 512)
                        : (y2 + ((size_t)(b * 256 + tt - 256)) * 512);
    } else {
        yp = y1 + (size_t)r * 512;
    }
    const float* p1 = a1 + (size_t)r * 512;
    const float* p2 = a2 + (size_t)r * 512;
    float z0 = sigmoidf_(p1[t])       * p2[t]       + yp[t];
    float z1 = sigmoidf_(p1[t + 256]) * p2[t + 256] + yp[t + 256];

    float s = z0 + z1;
#pragma unroll
    for (int o = 16; o > 0; o >>= 1) s += __shfl_xor_sync(0xffffffffu, s, o);
    if ((t & 31) == 0) red[t >> 5] = s;
    __syncthreads();
    if (t < 32) {
        float a = (t < 8) ? red[t] : 0.0f;
#pragma unroll
        for (int o = 4; o > 0; o >>= 1) a += __shfl_xor_sync(0xffffffffu, a, o);
        if (t == 0) red[0] = a;
    }
    __syncthreads();
    float mu = red[0] * (1.0f / 512.0f);
    float d0 = z0 - mu, d1 = z1 - mu;
    float s2 = d0 * d0 + d1 * d1;
    __syncthreads();
#pragma unroll
    for (int o = 16; o > 0; o >>= 1) s2 += __shfl_xor_sync(0xffffffffu, s2, o);
    if ((t & 31) == 0) red[t >> 5] = s2;
    __syncthreads();
    if (t < 32) {
        float a = (t < 8) ? red[t] : 0.0f;
#pragma unroll
        for (int o = 4; o > 0; o >>= 1) a += __shfl_xor_sync(0xffffffffu, a, o);
        if (t == 0) red[0] = a;
    }
    __syncthreads();
    float inv = rsqrtf(red[0] * (1.0f / 512.0f) + 1e-5f);
    outp[(size_t)r * 512 + t]       = gamma[t]       * d0 * inv + beta[t];
    outp[(size_t)r * 512 + t + 256] = gamma[t + 256] * d1 * inv + beta[t + 256];
}

// ========================= row softmax over 512 cols ==========================
__global__ __launch_bounds__(256) void softmax_k(
    const float* __restrict__ S, float* __restrict__ A)
{
    __shared__ float red[8];
    const int r = blockIdx.x;
    const int t = threadIdx.x;
    const float* p = S + (size_t)r * 512;
    float v0 = p[t], v1 = p[t + 256];
    float m = fmaxf(v0, v1);
#pragma unroll
    for (int o = 16; o > 0; o >>= 1) m = fmaxf(m, __shfl_xor_sync(0xffffffffu, m, o));
    if ((t & 31) == 0) red[t >> 5] = m;
    __syncthreads();
    if (t < 32) {
        float a = (t < 8) ? red[t] : -3.4e38f;
#pragma unroll
        for (int o = 4; o > 0; o >>= 1) a = fmaxf(a, __shfl_xor_sync(0xffffffffu, a, o));
        if (t == 0) red[0] = a;
    }
    __syncthreads();
    float mx = red[0];
    float e0 = expf(v0 - mx), e1 = expf(v1 - mx);
    float s = e0 + e1;
    __syncthreads();
#pragma unroll
    for (int o = 16; o > 0; o >>= 1) s += __shfl_xor_sync(0xffffffffu, s, o);
    if ((t & 31) == 0) red[t >> 5] = s;
    __syncthreads();
    if (t < 32) {
        float a = (t < 8) ? red[t] : 0.0f;
#pragma unroll
        for (int o = 4; o > 0; o >>= 1) a += __shfl_xor_sync(0xffffffffu, a, o);
        if (t == 0) red[0] = a;
    }
    __syncthreads();
    float inv = 1.0f / red[0];
    A[(size_t)r * 512 + t]       = e0 * inv;
    A[(size_t)r * 512 + t + 256] = e1 * inv;
}

// ================================= host =======================================
extern "C" void kernel_launch(void* const* d_in, const int* in_sizes, int n_in,
                              void* d_out, int out_size)
{
    const float* obs   = (const float*)d_in[0];
    const float* fut   = (const float*)d_in[1];
    const float* W_ih  = (const float*)d_in[2];
    const float* W_hh  = (const float*)d_in[3];
    const float* b_ih  = (const float*)d_in[4];
    const float* b_hh  = (const float*)d_in[5];
    const float* g1W1  = (const float*)d_in[6];
    const float* g1b1  = (const float*)d_in[7];
    const float* g1W2  = (const float*)d_in[8];
    const float* g1b2  = (const float*)d_in[9];
    const float* g1g   = (const float*)d_in[10];
    const float* g1b   = (const float*)d_in[11];
    const float* Wq    = (const float*)d_in[12];
    const float* bq    = (const float*)d_in[13];
    const float* Wk    = (const float*)d_in[14];
    const float* bk    = (const float*)d_in[15];
    const float* Wv    = (const float*)d_in[16];
    const float* bv    = (const float*)d_in[17];
    const float* Wo    = (const float*)d_in[18];
    const float* bo    = (const float*)d_in[19];
    const float* g2W1  = (const float*)d_in[20];
    const float* g2b1  = (const float*)d_in[21];
    const float* g2W2  = (const float*)d_in[22];
    const float* g2b2  = (const float*)d_in[23];
    const float* g2g   = (const float*)d_in[24];
    const float* g2b   = (const float*)d_in[25];

    float* out       = (float*)d_out;
    float* glu_delta = out;
    float* glu_phi   = out + (size_t)OUT1;
    float* attn      = out + (size_t)2 * OUT1;

    float *XG, *LH, *A1, *A2, *Qb, *Kb, *Vb;
    cudaGetSymbolAddress((void**)&XG, d_XG);
    cudaGetSymbolAddress((void**)&LH, d_LH);
    cudaGetSymbolAddress((void**)&A1, d_A1);
    cudaGetSymbolAddress((void**)&A2, d_A2);
    cudaGetSymbolAddress((void**)&Qb, d_Qb);
    cudaGetSymbolAddress((void**)&Kb, d_Kb);
    cudaGetSymbolAddress((void**)&Vb, d_Vb);

    // 1. X_gates = fut @ W_ih^T + (b_ih + b_hh)
    gemm_mma<<<dim3(G4 / 128, BF / 128), 256>>>(fut, W_ih, b_ih, b_hh, XG, BF, G4, Hd);

    // 2. lstm_hidden[:, :256, :] = vsn_observed
    copy_obs_k<<<(Bn * OBSn * Hd + 255) / 256, 256>>>(obs, LH);

    // 3. persistent LSTM over all 256 steps
    {
        const int smem = (64 * HSTRIDE + 16 * WSTRIDE) * 4;
        cudaFuncSetAttribute(lstm_persist, cudaFuncAttributeMaxDynamicSharedMemorySize, smem);
        lstm_persist<<<128, 256, smem>>>(obs, XG, W_hh, LH);
    }

    // 4. GLU-LN #1 -> glu_phi
    gemm_mma<<<dim3(4, 256), 256>>>(LH, g1W1, g1b1, nullptr, A1, BT, Hd, Hd);
    gemm_mma<<<dim3(4, 256), 256>>>(LH, g1W2, g1b2, nullptr, A2, BT, Hd, Hd);
    gluln_k<<<BT, 256>>>(A1, A2, obs, fut, g1g, g1b, glu_phi, 1);

    // 5. QKV
    gemm_mma<<<dim3(4, 256), 256>>>(glu_phi, Wq, bq, nullptr, Qb, BT, Hd, Hd);
    gemm_mma<<<dim3(4, 256), 256>>>(glu_phi, Wk, bk, nullptr, Kb, BT, Hd, Hd);
    gemm_mma<<<dim3(4, 256), 256>>>(glu_phi, Wv, bv, nullptr, Vb, BT, Hd, Hd);

    // 6. scores (reuse XG) + softmax -> attn
    gemm_tn_scores<<<dim3(4, 4, 64), 256>>>(Qb, Kb, XG, 0.04419417382415922f);
    softmax_k<<<BT, 256>>>(XG, attn);

    // 7. attn @ V -> reuse Qb; projection -> reuse Kb
    gemm_nn_b<<<dim3(4, 4, 64), 256>>>(attn, Vb, Qb);
    gemm_mma<<<dim3(4, 256), 256>>>(Qb, Wo, bo, nullptr, Kb, BT, Hd, Hd);

    // 8. GLU-LN #2 -> glu_delta
    gemm_mma<<<dim3(4, 256), 256>>>(Kb, g2W1, g2b1, nullptr, A1, BT, Hd, Hd);
    gemm_mma<<<dim3(4, 256), 256>>>(Kb, g2W2, g2b2, nullptr, A2, BT, Hd, Hd);
    gluln_k<<<BT, 256>>>(A1, A2, glu_phi, nullptr, g2g, g2b, glu_delta, 0);
}

// round 9
// speedup vs baseline: 2.5668x; 1.1096x over previous
#include <cuda_runtime.h>
#include <cstdint>
#include <cstddef>

// Problem dims
#define Hd    512
#define Bn    64
#define OBSn  256
#define FUTn  256
#define Tn    512
#define G4    2048
#define BT    32768
#define BF    16384
#define OUT1  16777216

// ---------------- scratch --------------------------------------------------
__device__ float d_XG[(size_t)BF * G4];
__device__ float d_LH[(size_t)BT * Hd];
__device__ float d_A1[(size_t)BT * Hd];
__device__ float d_A2[(size_t)BT * Hd];
__device__ float d_Qb[(size_t)BT * Hd];
__device__ float d_Kb[(size_t)BT * Hd];
__device__ float d_Vb[(size_t)BT * Hd];

__device__ unsigned g_bar_cnt = 0;
__device__ volatile unsigned g_bar_gen = 0;

__device__ __forceinline__ float sigmoidf_(float x) { return 1.0f / (1.0f + expf(-x)); }

// ---------------- mma.sync tf32 helpers --------------------------------------
__device__ __forceinline__ uint32_t f2tf32(float x) {
    uint32_t r;
    asm("cvt.rna.tf32.f32 %0, %1;" : "=r"(r) : "f"(x));
    return r;
}
__device__ __forceinline__ void mma_tf32(float* c, const uint32_t* a, const uint32_t* b) {
    asm volatile(
        "mma.sync.aligned.m16n8k8.row.col.f32.tf32.tf32.f32 "
        "{%0,%1,%2,%3}, {%4,%5,%6,%7}, {%8,%9}, {%0,%1,%2,%3};"
        : "+f"(c[0]), "+f"(c[1]), "+f"(c[2]), "+f"(c[3])
        : "r"(a[0]), "r"(a[1]), "r"(a[2]), "r"(a[3]), "r"(b[0]), "r"(b[1]));
}

// SMEM stride 136 floats: fragment LDS bank = (8q + g + c) % 32 -> 32 distinct.
#define SST 136

// ---- shared inner compute: one k16 stage of 8-warp 128x128 mma tile ---------
// af/bf fragments are read from [k][row] tf32 SMEM.
#define MMA_STAGE(Asrc, Wsrc, cacc)                                           \
    _Pragma("unroll")                                                         \
    for (int s_ = 0; s_ < 2; s_++) {                                          \
        const int kb_ = s_ * 8;                                               \
        uint32_t af_[4][4], bf_[4][2];                                        \
        _Pragma("unroll")                                                     \
        for (int mt_ = 0; mt_ < 4; mt_++) {                                   \
            int mr_ = wm + mt_ * 16 + g;                                      \
            af_[mt_][0] = (Asrc)[(kb_ + q) * SST + mr_];                      \
            af_[mt_][1] = (Asrc)[(kb_ + q) * SST + mr_ + 8];                  \
            af_[mt_][2] = (Asrc)[(kb_ + q + 4) * SST + mr_];                  \
            af_[mt_][3] = (Asrc)[(kb_ + q + 4) * SST + mr_ + 8];              \
        }                                                                     \
        _Pragma("unroll")                                                     \
        for (int nt_ = 0; nt_ < 4; nt_++) {                                   \
            int nc_ = wn + nt_ * 8 + g;                                       \
            bf_[nt_][0] = (Wsrc)[(kb_ + q) * SST + nc_];                      \
            bf_[nt_][1] = (Wsrc)[(kb_ + q + 4) * SST + nc_];                  \
        }                                                                     \
        _Pragma("unroll")                                                     \
        for (int mt_ = 0; mt_ < 4; mt_++)                                     \
            _Pragma("unroll")                                                 \
            for (int nt_ = 0; nt_ < 4; nt_++)                                 \
                mma_tf32((cacc)[mt_][nt_], af_[mt_], bf_[nt_]);               \
    }

// store 8 tf32 values into [k][row] SMEM
__device__ __forceinline__ void sts8_tf32(
    uint32_t* dst, int lk, int lr, float4 v0, float4 v1)
{
    dst[(lk + 0) * SST + lr] = f2tf32(v0.x);
    dst[(lk + 1) * SST + lr] = f2tf32(v0.y);
    dst[(lk + 2) * SST + lr] = f2tf32(v0.z);
    dst[(lk + 3) * SST + lr] = f2tf32(v0.w);
    dst[(lk + 4) * SST + lr] = f2tf32(v1.x);
    dst[(lk + 5) * SST + lr] = f2tf32(v1.y);
    dst[(lk + 6) * SST + lr] = f2tf32(v1.z);
    dst[(lk + 7) * SST + lr] = f2tf32(v1.w);
}

// =========== tf32 mma TN GEMM: C = A[M,K] @ W[N,K]^T + b1 + b2 ===============
__global__ __launch_bounds__(256) void gemm_mma(
    const float* __restrict__ A, const float* __restrict__ W,
    const float* __restrict__ b1, const float* __restrict__ b2,
    float* __restrict__ C, int M, int N, int K)
{
    __shared__ uint32_t As[2][16 * SST];
    __shared__ uint32_t Ws[2][16 * SST];
    __shared__ float bias_s[128];

    const int t = threadIdx.x, wid = t >> 5, lane = t & 31;
    const int m0 = blockIdx.y * 128, n0 = blockIdx.x * 128;
    const int wm = (wid >> 2) * 64, wn = (wid & 3) * 32;
    const int g = lane >> 2, q = lane & 3;

    if (t < 128) {
        float v = b1 ? b1[n0 + t] : 0.0f;
        if (b2) v += b2[n0 + t];
        bias_s[t] = v;
    }

    float c[4][4][4];
#pragma unroll
    for (int mt = 0; mt < 4; mt++)
#pragma unroll
        for (int nt = 0; nt < 4; nt++)
#pragma unroll
            for (int i = 0; i < 4; i++) c[mt][nt][i] = 0.0f;

    const int lr = t >> 1, lk = (t & 1) * 8;
    const float* Ap = A + (size_t)(m0 + lr) * K + lk;
    const float* Wp = W + (size_t)(n0 + lr) * K + lk;

    sts8_tf32(As[0], lk, lr, *(const float4*)Ap, *(const float4*)(Ap + 4));
    sts8_tf32(Ws[0], lk, lr, *(const float4*)Wp, *(const float4*)(Wp + 4));
    __syncthreads();

    int st = 0;
    for (int k0 = 0; k0 < K; k0 += 16) {
        float4 na0, na1, nw0, nw1;
        const bool more = (k0 + 16) < K;
        if (more) {
            na0 = *(const float4*)(Ap + k0 + 16);
            na1 = *(const float4*)(Ap + k0 + 20);
            nw0 = *(const float4*)(Wp + k0 + 16);
            nw1 = *(const float4*)(Wp + k0 + 20);
        }
        MMA_STAGE(As[st], Ws[st], c);
        if (more) {
            int ns = st ^ 1;
            sts8_tf32(As[ns], lk, lr, na0, na1);
            sts8_tf32(Ws[ns], lk, lr, nw0, nw1);
            __syncthreads();
            st = ns;
        }
    }

#pragma unroll
    for (int mt = 0; mt < 4; mt++) {
        int mrow = m0 + wm + mt * 16 + g;
#pragma unroll
        for (int nt = 0; nt < 4; nt++) {
            int ncol = wn + nt * 8 + 2 * q;
            float b0v = bias_s[ncol], b1v = bias_s[ncol + 1];
            float2 o0 = make_float2(c[mt][nt][0] + b0v, c[mt][nt][1] + b1v);
            float2 o1 = make_float2(c[mt][nt][2] + b0v, c[mt][nt][3] + b1v);
            *(float2*)&C[(size_t)mrow * N + n0 + ncol]       = o0;
            *(float2*)&C[(size_t)(mrow + 8) * N + n0 + ncol] = o1;
        }
    }
}

// ====== mma scores: S = scale*Q K^T, causal, triangle-skip ====================
__global__ __launch_bounds__(256) void gemm_mma_scores(
    const float* __restrict__ Qm, const float* __restrict__ Km,
    float* __restrict__ C, float scale)
{
    __shared__ uint32_t As[2][16 * SST];
    __shared__ uint32_t Ws[2][16 * SST];
    const size_t bo = (size_t)blockIdx.z * 262144;
    const int m0 = blockIdx.y * 128, n0 = blockIdx.x * 128;
    float* Cb = C + bo;
    const int t = threadIdx.x;

    if (n0 > m0 + 127) {
        float4 neg = make_float4(-1e30f, -1e30f, -1e30f, -1e30f);
        for (int idx = t; idx < 4096; idx += 256) {
            int r = idx >> 5, c4 = idx & 31;
            *(float4*)&Cb[(size_t)(m0 + r) * 512 + n0 + c4 * 4] = neg;
        }
        return;
    }

    const int wid = t >> 5, lane = t & 31;
    const int wm = (wid >> 2) * 64, wn = (wid & 3) * 32;
    const int g = lane >> 2, q = lane & 3;

    float c[4][4][4];
#pragma unroll
    for (int mt = 0; mt < 4; mt++)
#pragma unroll
        for (int nt = 0; nt < 4; nt++)
#pragma unroll
            for (int i = 0; i < 4; i++) c[mt][nt][i] = 0.0f;

    const int lr = t >> 1, lk = (t & 1) * 8;
    const float* Ap = Qm + bo + (size_t)(m0 + lr) * 512 + lk;
    const float* Wp = Km + bo + (size_t)(n0 + lr) * 512 + lk;

    sts8_tf32(As[0], lk, lr, *(const float4*)Ap, *(const float4*)(Ap + 4));
    sts8_tf32(Ws[0], lk, lr, *(const float4*)Wp, *(const float4*)(Wp + 4));
    __syncthreads();

    int st = 0;
    for (int k0 = 0; k0 < 512; k0 += 16) {
        float4 na0, na1, nw0, nw1;
        const bool more = (k0 + 16) < 512;
        if (more) {
            na0 = *(const float4*)(Ap + k0 + 16);
            na1 = *(const float4*)(Ap + k0 + 20);
            nw0 = *(const float4*)(Wp + k0 + 16);
            nw1 = *(const float4*)(Wp + k0 + 20);
        }
        MMA_STAGE(As[st], Ws[st], c);
        if (more) {
            int ns = st ^ 1;
            sts8_tf32(As[ns], lk, lr, na0, na1);
            sts8_tf32(Ws[ns], lk, lr, nw0, nw1);
            __syncthreads();
            st = ns;
        }
    }

#pragma unroll
    for (int mt = 0; mt < 4; mt++) {
        int q0 = m0 + wm + mt * 16 + g;
        int q1 = q0 + 8;
#pragma unroll
        for (int nt = 0; nt < 4; nt++) {
            int kk = n0 + wn + nt * 8 + 2 * q;
            float2 o0, o1;
            o0.x = (kk     > q0) ? -1e30f : c[mt][nt][0] * scale;
            o0.y = (kk + 1 > q0) ? -1e30f : c[mt][nt][1] * scale;
            o1.x = (kk     > q1) ? -1e30f : c[mt][nt][2] * scale;
            o1.y = (kk + 1 > q1) ? -1e30f : c[mt][nt][3] * scale;
            *(float2*)&Cb[(size_t)q0 * 512 + kk] = o0;
            *(float2*)&Cb[(size_t)q1 * 512 + kk] = o1;
        }
    }
}

// ====== mma AV: O = attn[512,512] @ V[512,512], K truncated (exact) ==========
__global__ __launch_bounds__(256) void gemm_mma_av(
    const float* __restrict__ Am, const float* __restrict__ Bm, float* __restrict__ C)
{
    __shared__ uint32_t As[2][16 * SST];
    __shared__ uint32_t Vs[2][16 * SST];
    const size_t bo = (size_t)blockIdx.z * 262144;
    const float* B = Bm + bo;
    float* Cb = C + bo;
    const int m0 = blockIdx.y * 128, n0 = blockIdx.x * 128;
    const int Kmax = m0 + 128;
    const int t = threadIdx.x, wid = t >> 5, lane = t & 31;
    const int wm = (wid >> 2) * 64, wn = (wid & 3) * 32;
    const int g = lane >> 2, q = lane & 3;

    float c[4][4][4];
#pragma unroll
    for (int mt = 0; mt < 4; mt++)
#pragma unroll
        for (int nt = 0; nt < 4; nt++)
#pragma unroll
            for (int i = 0; i < 4; i++) c[mt][nt][i] = 0.0f;

    const int lr = t >> 1, lk = (t & 1) * 8;
    const float* Ap = Am + bo + (size_t)(m0 + lr) * 512 + lk;
    // V loader: row kr (0..15), col group (t&15)*8
    const int vkr = t >> 4, vnc = (t & 15) * 8;
    const float* Vp = B + (size_t)vkr * 512 + n0 + vnc;

    {
        sts8_tf32(As[0], lk, lr, *(const float4*)Ap, *(const float4*)(Ap + 4));
        float4 v0 = *(const float4*)(Vp);
        float4 v1 = *(const float4*)(Vp + 4);
        uint32_t* d = &Vs[0][vkr * SST + vnc];
        d[0] = f2tf32(v0.x); d[1] = f2tf32(v0.y); d[2] = f2tf32(v0.z); d[3] = f2tf32(v0.w);
        d[4] = f2tf32(v1.x); d[5] = f2tf32(v1.y); d[6] = f2tf32(v1.z); d[7] = f2tf32(v1.w);
    }
    __syncthreads();

    int st = 0;
    for (int k0 = 0; k0 < Kmax; k0 += 16) {
        float4 na0, na1, nv0, nv1;
        const bool more = (k0 + 16) < Kmax;
        if (more) {
            na0 = *(const float4*)(Ap + k0 + 16);
            na1 = *(const float4*)(Ap + k0 + 20);
            nv0 = *(const float4*)(Vp + (size_t)(k0 + 16) * 512);
            nv1 = *(const float4*)(Vp + (size_t)(k0 + 16) * 512 + 4);
        }
        MMA_STAGE(As[st], Vs[st], c);
        if (more) {
            int ns = st ^ 1;
            sts8_tf32(As[ns], lk, lr, na0, na1);
            uint32_t* d = &Vs[ns][vkr * SST + vnc];
            d[0] = f2tf32(nv0.x); d[1] = f2tf32(nv0.y); d[2] = f2tf32(nv0.z); d[3] = f2tf32(nv0.w);
            d[4] = f2tf32(nv1.x); d[5] = f2tf32(nv1.y); d[6] = f2tf32(nv1.z); d[7] = f2tf32(nv1.w);
            __syncthreads();
            st = ns;
        }
    }

#pragma unroll
    for (int mt = 0; mt < 4; mt++) {
        int mrow = m0 + wm + mt * 16 + g;
#pragma unroll
        for (int nt = 0; nt < 4; nt++) {
            int ncol = wn + nt * 8 + 2 * q;
            float2 o0 = make_float2(c[mt][nt][0], c[mt][nt][1]);
            float2 o1 = make_float2(c[mt][nt][2], c[mt][nt][3]);
            *(float2*)&Cb[(size_t)mrow * 512 + n0 + ncol]       = o0;
            *(float2*)&Cb[(size_t)(mrow + 8) * 512 + n0 + ncol] = o1;
        }
    }
}

// ======================= copy observed rows into lstm_hidden ==================
__global__ void copy_obs_k(const float* __restrict__ obs, float* __restrict__ LH)
{
    size_t i = (size_t)blockIdx.x * blockDim.x + threadIdx.x;
    if (i < (size_t)Bn * OBSn * Hd) {
        size_t b = i >> 17;
        size_t rem = i & 131071;
        LH[b * 262144 + rem] = obs[i];
    }
}

// ============ persistent LSTM (v4: passing) ===================================
#define HSTRIDE 516
#define WSTRIDE 512
__global__ __launch_bounds__(256, 1) void lstm_persist(
    const float* __restrict__ obs, const float* __restrict__ XG,
    const float* __restrict__ Whh, float* __restrict__ LH)
{
    extern __shared__ float sh[];
    float* Hs = sh;
    float* Ws = sh + 64 * HSTRIDE;
    __shared__ float gsm[4 * 64 * 4];

    const int t = threadIdx.x;
    const int ublk = blockIdx.x * 4;
    const unsigned nb = gridDim.x;

    for (int idx = t; idx < 16 * 128; idx += 256) {
        int row = idx >> 7, qq = idx & 127;
        int g = row >> 2, j = row & 3;
        float4 v = *(const float4*)(Whh + (size_t)(g * 512 + ublk + j) * 512 + qq * 4);
        *(float4*)(Ws + row * WSTRIDE + qq * 4) = v;
    }

    const int wid = t >> 5, lane = t & 31;
    const int g = wid >> 1, bh = wid & 1;
    const int batch = bh * 32 + lane;

    const int pb = t >> 2, pj = t & 3;
    float c_reg = obs[(size_t)pb * 131072 + 255 * 512 + ublk + pj];

    const int crow = t >> 7;
    const int ccol = (t & 127) * 4;

    for (int s = 0; s < 256; s++) {
        const float* xrow = XG + (size_t)(pb * 256 + s) * 2048 + ublk + pj;
        float xg0 = __ldcg(xrow);
        float xg1 = __ldcg(xrow + 512);
        float xg2 = __ldcg(xrow + 1024);
        float xg3 = __ldcg(xrow + 1536);

        {
            const float* hsrc; size_t hstr;
            if (s == 0) { hsrc = obs + 255 * 512; hstr = 131072; }
            else        { hsrc = LH + (size_t)(255 + s) * 512; hstr = 262144; }
#pragma unroll
            for (int i = 0; i < 32; i++) {
                int r = 2 * i + crow;
                float4 v = __ldcg((const float4*)(hsrc + (size_t)r * hstr + ccol));
                *(float4*)(Hs + r * HSTRIDE + ccol) = v;
            }
        }
        __syncthreads();

        {
            const float* xp = Hs + batch * HSTRIDE;
            const float* wp = Ws + (g * 4) * WSTRIDE;
            float a0 = 0.f, a1 = 0.f, a2 = 0.f, a3 = 0.f;
#pragma unroll 8
            for (int k0 = 0; k0 < 512; k0 += 4) {
                float4 xv = *(const float4*)(xp + k0);
                float4 w0 = *(const float4*)(wp + k0);
                float4 w1 = *(const float4*)(wp + WSTRIDE + k0);
                float4 w2 = *(const float4*)(wp + 2 * WSTRIDE + k0);
                float4 w3 = *(const float4*)(wp + 3 * WSTRIDE + k0);
                a0 += xv.x * w0.x + xv.y * w0.y + xv.z * w0.z + xv.w * w0.w;
                a1 += xv.x * w1.x + xv.y * w1.y + xv.z * w1.z + xv.w * w1.w;
                a2 += xv.x * w2.x + xv.y * w2.y + xv.z * w2.z + xv.w * w2.w;
                a3 += xv.x * w3.x + xv.y * w3.y + xv.z * w3.z + xv.w * w3.w;
            }
            float4 o; o.x = a0; o.y = a1; o.z = a2; o.w = a3;
            *(float4*)(gsm + (g * 64 + batch) * 4) = o;
        }
        __syncthreads();

        {
            float gi = gsm[(0 * 64 + pb) * 4 + pj] + xg0;
            float gf = gsm[(1 * 64 + pb) * 4 + pj] + xg1;
            float gg = gsm[(2 * 64 + pb) * 4 + pj] + xg2;
            float go = gsm[(3 * 64 + pb) * 4 + pj] + xg3;
            c_reg = sigmoidf_(gf) * c_reg + sigmoidf_(gi) * tanhf(gg);
            float hv = sigmoidf_(go) * tanhf(c_reg);
            LH[(size_t)pb * 262144 + (size_t)(256 + s) * 512 + ublk + pj] = hv;
        }

        __threadfence();
        __syncthreads();
        if (t == 0) {
            unsigned snap = g_bar_gen;
            unsigned old = atomicAdd(&g_bar_cnt, 1u);
            if (old == nb - 1u) {
                g_bar_cnt = 0;
                __threadfence();
                g_bar_gen = snap + 1u;
            } else {
                while (g_bar_gen == snap) __nanosleep(32);
            }
            __threadfence();
        }
        __syncthreads();
    }
}

// ====================== fused GLU + LayerNorm =================================
__global__ __launch_bounds__(256) void gluln_k(
    const float* __restrict__ a1, const float* __restrict__ a2,
    const float* __restrict__ y1, const float* __restrict__ y2,
    const float* __restrict__ gamma, const float* __restrict__ beta,
    float* __restrict__ outp, int splitY)
{
    __shared__ float red[8];
    const int r = blockIdx.x;
    const int t = threadIdx.x;
    const float* yp;
    if (splitY) {
        int b = r >> 9, tt = r & 511;
        yp = (tt < 256) ? (y1 + ((size_t)(b * 256 + tt)) * 512)
                        : (y2 + ((size_t)(b * 256 + tt - 256)) * 512);
    } else {
        yp = y1 + (size_t)r * 512;
    }
    const float* p1 = a1 + (size_t)r * 512;
    const float* p2 = a2 + (size_t)r * 512;
    float z0 = sigmoidf_(p1[t])       * p2[t]       + yp[t];
    float z1 = sigmoidf_(p1[t + 256]) * p2[t + 256] + yp[t + 256];

    float s = z0 + z1;
#pragma unroll
    for (int o = 16; o > 0; o >>= 1) s += __shfl_xor_sync(0xffffffffu, s, o);
    if ((t & 31) == 0) red[t >> 5] = s;
    __syncthreads();
    if (t < 32) {
        float a = (t < 8) ? red[t] : 0.0f;
#pragma unroll
        for (int o = 4; o > 0; o >>= 1) a += __shfl_xor_sync(0xffffffffu, a, o);
        if (t == 0) red[0] = a;
    }
    __syncthreads();
    float mu = red[0] * (1.0f / 512.0f);
    float d0 = z0 - mu, d1 = z1 - mu;
    float s2 = d0 * d0 + d1 * d1;
    __syncthreads();
#pragma unroll
    for (int o = 16; o > 0; o >>= 1) s2 += __shfl_xor_sync(0xffffffffu, s2, o);
    if ((t & 31) == 0) red[t >> 5] = s2;
    __syncthreads();
    if (t < 32) {
        float a = (t < 8) ? red[t] : 0.0f;
#pragma unroll
        for (int o = 4; o > 0; o >>= 1) a += __shfl_xor_sync(0xffffffffu, a, o);
        if (t == 0) red[0] = a;
    }
    __syncthreads();
    float inv = rsqrtf(red[0] * (1.0f / 512.0f) + 1e-5f);
    outp[(size_t)r * 512 + t]       = gamma[t]       * d0 * inv + beta[t];
    outp[(size_t)r * 512 + t + 256] = gamma[t + 256] * d1 * inv + beta[t + 256];
}

// ========================= row softmax over 512 cols ==========================
__global__ __launch_bounds__(256) void softmax_k(
    const float* __restrict__ S, float* __restrict__ A)
{
    __shared__ float red[8];
    const int r = blockIdx.x;
    const int t = threadIdx.x;
    const float* p = S + (size_t)r * 512;
    float v0 = p[t], v1 = p[t + 256];
    float m = fmaxf(v0, v1);
#pragma unroll
    for (int o = 16; o > 0; o >>= 1) m = fmaxf(m, __shfl_xor_sync(0xffffffffu, m, o));
    if ((t & 31) == 0) red[t >> 5] = m;
    __syncthreads();
    if (t < 32) {
        float a = (t < 8) ? red[t] : -3.4e38f;
#pragma unroll
        for (int o = 4; o > 0; o >>= 1) a = fmaxf(a, __shfl_xor_sync(0xffffffffu, a, o));
        if (t == 0) red[0] = a;
    }
    __syncthreads();
    float mx = red[0];
    float e0 = expf(v0 - mx), e1 = expf(v1 - mx);
    float s = e0 + e1;
    __syncthreads();
#pragma unroll
    for (int o = 16; o > 0; o >>= 1) s += __shfl_xor_sync(0xffffffffu, s, o);
    if ((t & 31) == 0) red[t >> 5] = s;
    __syncthreads();
    if (t < 32) {
        float a = (t < 8) ? red[t] : 0.0f;
#pragma unroll
        for (int o = 4; o > 0; o >>= 1) a += __shfl_xor_sync(0xffffffffu, a, o);
        if (t == 0) red[0] = a;
    }
    __syncthreads();
    float inv = 1.0f / red[0];
    A[(size_t)r * 512 + t]       = e0 * inv;
    A[(size_t)r * 512 + t + 256] = e1 * inv;
}

// ================================= host =======================================
extern "C" void kernel_launch(void* const* d_in, const int* in_sizes, int n_in,
                              void* d_out, int out_size)
{
    const float* obs   = (const float*)d_in[0];
    const float* fut   = (const float*)d_in[1];
    const float* W_ih  = (const float*)d_in[2];
    const float* W_hh  = (const float*)d_in[3];
    const float* b_ih  = (const float*)d_in[4];
    const float* b_hh  = (const float*)d_in[5];
    const float* g1W1  = (const float*)d_in[6];
    const float* g1b1  = (const float*)d_in[7];
    const float* g1W2  = (const float*)d_in[8];
    const float* g1b2  = (const float*)d_in[9];
    const float* g1g   = (const float*)d_in[10];
    const float* g1b   = (const float*)d_in[11];
    const float* Wq    = (const float*)d_in[12];
    const float* bq    = (const float*)d_in[13];
    const float* Wk    = (const float*)d_in[14];
    const float* bk    = (const float*)d_in[15];
    const float* Wv    = (const float*)d_in[16];
    const float* bv    = (const float*)d_in[17];
    const float* Wo    = (const float*)d_in[18];
    const float* bo    = (const float*)d_in[19];
    const float* g2W1  = (const float*)d_in[20];
    const float* g2b1  = (const float*)d_in[21];
    const float* g2W2  = (const float*)d_in[22];
    const float* g2b2  = (const float*)d_in[23];
    const float* g2g   = (const float*)d_in[24];
    const float* g2b   = (const float*)d_in[25];

    float* out       = (float*)d_out;
    float* glu_delta = out;
    float* glu_phi   = out + (size_t)OUT1;
    float* attn      = out + (size_t)2 * OUT1;

    float *XG, *LH, *A1, *A2, *Qb, *Kb, *Vb;
    cudaGetSymbolAddress((void**)&XG, d_XG);
    cudaGetSymbolAddress((void**)&LH, d_LH);
    cudaGetSymbolAddress((void**)&A1, d_A1);
    cudaGetSymbolAddress((void**)&A2, d_A2);
    cudaGetSymbolAddress((void**)&Qb, d_Qb);
    cudaGetSymbolAddress((void**)&Kb, d_Kb);
    cudaGetSymbolAddress((void**)&Vb, d_Vb);

    // 1. X_gates = fut @ W_ih^T + (b_ih + b_hh)
    gemm_mma<<<dim3(G4 / 128, BF / 128), 256>>>(fut, W_ih, b_ih, b_hh, XG, BF, G4, Hd);

    // 2. lstm_hidden[:, :256, :] = vsn_observed
    copy_obs_k<<<(Bn * OBSn * Hd + 255) / 256, 256>>>(obs, LH);

    // 3. persistent LSTM over all 256 steps
    {
        const int smem = (64 * HSTRIDE + 16 * WSTRIDE) * 4;
        cudaFuncSetAttribute(lstm_persist, cudaFuncAttributeMaxDynamicSharedMemorySize, smem);
        lstm_persist<<<128, 256, smem>>>(obs, XG, W_hh, LH);
    }

    // 4. GLU-LN #1 -> glu_phi
    gemm_mma<<<dim3(4, 256), 256>>>(LH, g1W1, g1b1, nullptr, A1, BT, Hd, Hd);
    gemm_mma<<<dim3(4, 256), 256>>>(LH, g1W2, g1b2, nullptr, A2, BT, Hd, Hd);
    gluln_k<<<BT, 256>>>(A1, A2, obs, fut, g1g, g1b, glu_phi, 1);

    // 5. QKV
    gemm_mma<<<dim3(4, 256), 256>>>(glu_phi, Wq, bq, nullptr, Qb, BT, Hd, Hd);
    gemm_mma<<<dim3(4, 256), 256>>>(glu_phi, Wk, bk, nullptr, Kb, BT, Hd, Hd);
    gemm_mma<<<dim3(4, 256), 256>>>(glu_phi, Wv, bv, nullptr, Vb, BT, Hd, Hd);

    // 6. scores (reuse XG) + softmax -> attn
    gemm_mma_scores<<<dim3(4, 4, 64), 256>>>(Qb, Kb, XG, 0.04419417382415922f);
    softmax_k<<<BT, 256>>>(XG, attn);

    // 7. attn @ V -> reuse Qb; projection -> reuse Kb
    gemm_mma_av<<<dim3(4, 4, 64), 256>>>(attn, Vb, Qb);
    gemm_mma<<<dim3(4, 256), 256>>>(Qb, Wo, bo, nullptr, Kb, BT, Hd, Hd);

    // 8. GLU-LN #2 -> glu_delta
    gemm_mma<<<dim3(4, 256), 256>>>(Kb, g2W1, g2b1, nullptr, A1, BT, Hd, Hd);
    gemm_mma<<<dim3(4, 256), 256>>>(Kb, g2W2, g2b2, nullptr, A2, BT, Hd, Hd);
    gluln_k<<<BT, 256>>>(A1, A2, glu_phi, nullptr, g2g, g2b, glu_delta, 0);
}

// round 10
// speedup vs baseline: 2.6526x; 1.0334x over previous
#include <cuda_runtime.h>
#include <cstdint>
#include <cstddef>

// Problem dims
#define Hd    512
#define Bn    64
#define OBSn  256
#define FUTn  256
#define Tn    512
#define G4    2048
#define BT    32768
#define BF    16384
#define OUT1  16777216

// ---------------- scratch --------------------------------------------------
__device__ float d_XG[(size_t)BF * G4];
__device__ float d_LH[(size_t)BT * Hd];
__device__ float d_A1[(size_t)BT * Hd];
__device__ float d_A2[(size_t)BT * Hd];
__device__ float d_Qb[(size_t)BT * Hd];
__device__ float d_Kb[(size_t)BT * Hd];
__device__ float d_Vb[(size_t)BT * Hd];

__device__ unsigned g_bar_cnt = 0;
__device__ volatile unsigned g_bar_gen = 0;

__device__ __forceinline__ float sigmoidf_(float x) { return 1.0f / (1.0f + expf(-x)); }

// ---------------- mma.sync tf32 helpers --------------------------------------
__device__ __forceinline__ uint32_t f2tf32(float x) {
    uint32_t r;
    asm("cvt.rna.tf32.f32 %0, %1;" : "=r"(r) : "f"(x));
    return r;
}
__device__ __forceinline__ void mma_tf32(float* c, const uint32_t* a, const uint32_t* b) {
    asm volatile(
        "mma.sync.aligned.m16n8k8.row.col.f32.tf32.tf32.f32 "
        "{%0,%1,%2,%3}, {%4,%5,%6,%7}, {%8,%9}, {%0,%1,%2,%3};"
        : "+f"(c[0]), "+f"(c[1]), "+f"(c[2]), "+f"(c[3])
        : "r"(a[0]), "r"(a[1]), "r"(a[2]), "r"(a[3]), "r"(b[0]), "r"(b[1]));
}

// ---- k-permuted SMEM layout: per k8 group, word = row*8 + p,
//      p=2q holds k=q, p=2q+1 holds k=q+4. group stride 1032 words.
#define GSTRIDE 1032
#define STAGEW  (2 * GSTRIDE)

// store 8 k-consecutive tf32 values (one k8 group) permuted, 2x STS.128
__device__ __forceinline__ void sts_perm(
    uint32_t* base, int gidx, int lr, float4 v0, float4 v1)
{
    uint32_t* d = base + gidx * GSTRIDE + lr * 8;
    uint4 w0, w1;
    w0.x = f2tf32(v0.x); w0.y = f2tf32(v1.x); w0.z = f2tf32(v0.y); w0.w = f2tf32(v1.y);
    w1.x = f2tf32(v0.z); w1.y = f2tf32(v1.z); w1.z = f2tf32(v0.w); w1.w = f2tf32(v1.w);
    *(uint4*)(d)     = w0;
    *(uint4*)(d + 4) = w1;
}

// one k16 stage, permuted layout both operands (LDS.64 fragment loads)
#define MMA_STAGE_P(Asrc, Wsrc, cacc)                                         \
    _Pragma("unroll")                                                         \
    for (int s_ = 0; s_ < 2; s_++) {                                          \
        const uint32_t* Ag_ = (Asrc) + s_ * GSTRIDE;                          \
        const uint32_t* Wg_ = (Wsrc) + s_ * GSTRIDE;                          \
        uint32_t af_[4][4], bf_[4][2];                                        \
        _Pragma("unroll")                                                     \
        for (int mt_ = 0; mt_ < 4; mt_++) {                                   \
            int mr_ = wm + mt_ * 16 + g;                                      \
            uint2 u0_ = *(const uint2*)&Ag_[mr_ * 8 + 2 * q];                 \
            uint2 u1_ = *(const uint2*)&Ag_[(mr_ + 8) * 8 + 2 * q];           \
            af_[mt_][0] = u0_.x; af_[mt_][1] = u1_.x;                         \
            af_[mt_][2] = u0_.y; af_[mt_][3] = u1_.y;                         \
        }                                                                     \
        _Pragma("unroll")                                                     \
        for (int nt_ = 0; nt_ < 4; nt_++) {                                   \
            int nc_ = wn + nt_ * 8 + g;                                       \
            uint2 u_ = *(const uint2*)&Wg_[nc_ * 8 + 2 * q];                  \
            bf_[nt_][0] = u_.x; bf_[nt_][1] = u_.y;                           \
        }                                                                     \
        _Pragma("unroll")                                                     \
        for (int mt_ = 0; mt_ < 4; mt_++)                                     \
            _Pragma("unroll")                                                 \
            for (int nt_ = 0; nt_ < 4; nt_++)                                 \
                mma_tf32((cacc)[mt_][nt_], af_[mt_], bf_[nt_]);               \
    }

// one k16 stage: A permuted (LDS.64), W old [k][SST] layout (scalar LDS)
#define SST 136
#define MMA_STAGE_AV(Asrc, Wsrc, cacc)                                        \
    _Pragma("unroll")                                                         \
    for (int s_ = 0; s_ < 2; s_++) {                                          \
        const uint32_t* Ag_ = (Asrc) + s_ * GSTRIDE;                          \
        const int kb_ = s_ * 8;                                               \
        uint32_t af_[4][4], bf_[4][2];                                        \
        _Pragma("unroll")                                                     \
        for (int mt_ = 0; mt_ < 4; mt_++) {                                   \
            int mr_ = wm + mt_ * 16 + g;                                      \
            uint2 u0_ = *(const uint2*)&Ag_[mr_ * 8 + 2 * q];                 \
            uint2 u1_ = *(const uint2*)&Ag_[(mr_ + 8) * 8 + 2 * q];           \
            af_[mt_][0] = u0_.x; af_[mt_][1] = u1_.x;                         \
            af_[mt_][2] = u0_.y; af_[mt_][3] = u1_.y;                         \
        }                                                                     \
        _Pragma("unroll")                                                     \
        for (int nt_ = 0; nt_ < 4; nt_++) {                                   \
            int nc_ = wn + nt_ * 8 + g;                                       \
            bf_[nt_][0] = (Wsrc)[(kb_ + q) * SST + nc_];                      \
            bf_[nt_][1] = (Wsrc)[(kb_ + q + 4) * SST + nc_];                  \
        }                                                                     \
        _Pragma("unroll")                                                     \
        for (int mt_ = 0; mt_ < 4; mt_++)                                     \
            _Pragma("unroll")                                                 \
            for (int nt_ = 0; nt_ < 4; nt_++)                                 \
                mma_tf32((cacc)[mt_][nt_], af_[mt_], bf_[nt_]);               \
    }

// =========== tf32 mma TN GEMM: C = A[M,K] @ W[N,K]^T + b1 + b2 ===============
__global__ __launch_bounds__(256) void gemm_mma(
    const float* __restrict__ A, const float* __restrict__ W,
    const float* __restrict__ b1, const float* __restrict__ b2,
    float* __restrict__ C, int M, int N, int K)
{
    __shared__ uint32_t As[2][STAGEW];
    __shared__ uint32_t Ws[2][STAGEW];
    __shared__ float bias_s[128];

    const int t = threadIdx.x, wid = t >> 5, lane = t & 31;
    const int m0 = blockIdx.y * 128, n0 = blockIdx.x * 128;
    const int wm = (wid >> 2) * 64, wn = (wid & 3) * 32;
    const int g = lane >> 2, q = lane & 3;

    if (t < 128) {
        float v = b1 ? b1[n0 + t] : 0.0f;
        if (b2) v += b2[n0 + t];
        bias_s[t] = v;
    }

    float c[4][4][4];
#pragma unroll
    for (int mt = 0; mt < 4; mt++)
#pragma unroll
        for (int nt = 0; nt < 4; nt++)
#pragma unroll
            for (int i = 0; i < 4; i++) c[mt][nt][i] = 0.0f;

    const int lr = t >> 1, gx = t & 1, lk = gx * 8;
    const float* Ap = A + (size_t)(m0 + lr) * K + lk;
    const float* Wp = W + (size_t)(n0 + lr) * K + lk;

    sts_perm(As[0], gx, lr, *(const float4*)Ap, *(const float4*)(Ap + 4));
    sts_perm(Ws[0], gx, lr, *(const float4*)Wp, *(const float4*)(Wp + 4));
    __syncthreads();

    int st = 0;
    for (int k0 = 0; k0 < K; k0 += 16) {
        float4 na0, na1, nw0, nw1;
        const bool more = (k0 + 16) < K;
        if (more) {
            na0 = *(const float4*)(Ap + k0 + 16);
            na1 = *(const float4*)(Ap + k0 + 20);
            nw0 = *(const float4*)(Wp + k0 + 16);
            nw1 = *(const float4*)(Wp + k0 + 20);
        }
        MMA_STAGE_P(As[st], Ws[st], c);
        if (more) {
            int ns = st ^ 1;
            sts_perm(As[ns], gx, lr, na0, na1);
            sts_perm(Ws[ns], gx, lr, nw0, nw1);
            __syncthreads();
            st = ns;
        }
    }

#pragma unroll
    for (int mt = 0; mt < 4; mt++) {
        int mrow = m0 + wm + mt * 16 + g;
#pragma unroll
        for (int nt = 0; nt < 4; nt++) {
            int ncol = wn + nt * 8 + 2 * q;
            float b0v = bias_s[ncol], b1v = bias_s[ncol + 1];
            float2 o0 = make_float2(c[mt][nt][0] + b0v, c[mt][nt][1] + b1v);
            float2 o1 = make_float2(c[mt][nt][2] + b0v, c[mt][nt][3] + b1v);
            *(float2*)&C[(size_t)mrow * N + n0 + ncol]       = o0;
            *(float2*)&C[(size_t)(mrow + 8) * N + n0 + ncol] = o1;
        }
    }
}

// ====== mma scores: S = scale*Q K^T, causal, triangle-skip ====================
__global__ __launch_bounds__(256) void gemm_mma_scores(
    const float* __restrict__ Qm, const float* __restrict__ Km,
    float* __restrict__ C, float scale)
{
    __shared__ uint32_t As[2][STAGEW];
    __shared__ uint32_t Ws[2][STAGEW];
    const size_t bo = (size_t)blockIdx.z * 262144;
    const int m0 = blockIdx.y * 128, n0 = blockIdx.x * 128;
    float* Cb = C + bo;
    const int t = threadIdx.x;

    if (n0 > m0 + 127) {
        float4 neg = make_float4(-1e30f, -1e30f, -1e30f, -1e30f);
        for (int idx = t; idx < 4096; idx += 256) {
            int r = idx >> 5, c4 = idx & 31;
            *(float4*)&Cb[(size_t)(m0 + r) * 512 + n0 + c4 * 4] = neg;
        }
        return;
    }

    const int wid = t >> 5, lane = t & 31;
    const int wm = (wid >> 2) * 64, wn = (wid & 3) * 32;
    const int g = lane >> 2, q = lane & 3;

    float c[4][4][4];
#pragma unroll
    for (int mt = 0; mt < 4; mt++)
#pragma unroll
        for (int nt = 0; nt < 4; nt++)
#pragma unroll
            for (int i = 0; i < 4; i++) c[mt][nt][i] = 0.0f;

    const int lr = t >> 1, gx = t & 1, lk = gx * 8;
    const float* Ap = Qm + bo + (size_t)(m0 + lr) * 512 + lk;
    const float* Wp = Km + bo + (size_t)(n0 + lr) * 512 + lk;

    sts_perm(As[0], gx, lr, *(const float4*)Ap, *(const float4*)(Ap + 4));
    sts_perm(Ws[0], gx, lr, *(const float4*)Wp, *(const float4*)(Wp + 4));
    __syncthreads();

    int st = 0;
    for (int k0 = 0; k0 < 512; k0 += 16) {
        float4 na0, na1, nw0, nw1;
        const bool more = (k0 + 16) < 512;
        if (more) {
            na0 = *(const float4*)(Ap + k0 + 16);
            na1 = *(const float4*)(Ap + k0 + 20);
            nw0 = *(const float4*)(Wp + k0 + 16);
            nw1 = *(const float4*)(Wp + k0 + 20);
        }
        MMA_STAGE_P(As[st], Ws[st], c);
        if (more) {
            int ns = st ^ 1;
            sts_perm(As[ns], gx, lr, na0, na1);
            sts_perm(Ws[ns], gx, lr, nw0, nw1);
            __syncthreads();
            st = ns;
        }
    }

#pragma unroll
    for (int mt = 0; mt < 4; mt++) {
        int q0 = m0 + wm + mt * 16 + g;
        int q1 = q0 + 8;
#pragma unroll
        for (int nt = 0; nt < 4; nt++) {
            int kk = n0 + wn + nt * 8 + 2 * q;
            float2 o0, o1;
            o0.x = (kk     > q0) ? -1e30f : c[mt][nt][0] * scale;
            o0.y = (kk + 1 > q0) ? -1e30f : c[mt][nt][1] * scale;
            o1.x = (kk     > q1) ? -1e30f : c[mt][nt][2] * scale;
            o1.y = (kk + 1 > q1) ? -1e30f : c[mt][nt][3] * scale;
            *(float2*)&Cb[(size_t)q0 * 512 + kk] = o0;
            *(float2*)&Cb[(size_t)q1 * 512 + kk] = o1;
        }
    }
}

// ====== mma AV: O = attn @ V, K truncated (exact) =============================
__global__ __launch_bounds__(256) void gemm_mma_av(
    const float* __restrict__ Am, const float* __restrict__ Bm, float* __restrict__ C)
{
    __shared__ uint32_t As[2][STAGEW];
    __shared__ uint32_t Vs[2][16 * SST];
    const size_t bo = (size_t)blockIdx.z * 262144;
    const float* B = Bm + bo;
    float* Cb = C + bo;
    const int m0 = blockIdx.y * 128, n0 = blockIdx.x * 128;
    const int Kmax = m0 + 128;
    const int t = threadIdx.x, wid = t >> 5, lane = t & 31;
    const int wm = (wid >> 2) * 64, wn = (wid & 3) * 32;
    const int g = lane >> 2, q = lane & 3;

    float c[4][4][4];
#pragma unroll
    for (int mt = 0; mt < 4; mt++)
#pragma unroll
        for (int nt = 0; nt < 4; nt++)
#pragma unroll
            for (int i = 0; i < 4; i++) c[mt][nt][i] = 0.0f;

    const int lr = t >> 1, gx = t & 1, lk = gx * 8;
    const float* Ap = Am + bo + (size_t)(m0 + lr) * 512 + lk;
    const int vkr = t >> 4, vnc = (t & 15) * 8;
    const float* Vp = B + (size_t)vkr * 512 + n0 + vnc;

    {
        sts_perm(As[0], gx, lr, *(const float4*)Ap, *(const float4*)(Ap + 4));
        float4 v0 = *(const float4*)(Vp);
        float4 v1 = *(const float4*)(Vp + 4);
        uint32_t* d = &Vs[0][vkr * SST + vnc];
        d[0] = f2tf32(v0.x); d[1] = f2tf32(v0.y); d[2] = f2tf32(v0.z); d[3] = f2tf32(v0.w);
        d[4] = f2tf32(v1.x); d[5] = f2tf32(v1.y); d[6] = f2tf32(v1.z); d[7] = f2tf32(v1.w);
    }
    __syncthreads();

    int st = 0;
    for (int k0 = 0; k0 < Kmax; k0 += 16) {
        float4 na0, na1, nv0, nv1;
        const bool more = (k0 + 16) < Kmax;
        if (more) {
            na0 = *(const float4*)(Ap + k0 + 16);
            na1 = *(const float4*)(Ap + k0 + 20);
            nv0 = *(const float4*)(Vp + (size_t)(k0 + 16) * 512);
            nv1 = *(const float4*)(Vp + (size_t)(k0 + 16) * 512 + 4);
        }
        MMA_STAGE_AV(As[st], Vs[st], c);
        if (more) {
            int ns = st ^ 1;
            sts_perm(As[ns], gx, lr, na0, na1);
            uint32_t* d = &Vs[ns][vkr * SST + vnc];
            d[0] = f2tf32(nv0.x); d[1] = f2tf32(nv0.y); d[2] = f2tf32(nv0.z); d[3] = f2tf32(nv0.w);
            d[4] = f2tf32(nv1.x); d[5] = f2tf32(nv1.y); d[6] = f2tf32(nv1.z); d[7] = f2tf32(nv1.w);
            __syncthreads();
            st = ns;
        }
    }

#pragma unroll
    for (int mt = 0; mt < 4; mt++) {
        int mrow = m0 + wm + mt * 16 + g;
#pragma unroll
        for (int nt = 0; nt < 4; nt++) {
            int ncol = wn + nt * 8 + 2 * q;
            float2 o0 = make_float2(c[mt][nt][0], c[mt][nt][1]);
            float2 o1 = make_float2(c[mt][nt][2], c[mt][nt][3]);
            *(float2*)&Cb[(size_t)mrow * 512 + n0 + ncol]       = o0;
            *(float2*)&Cb[(size_t)(mrow + 8) * 512 + n0 + ncol] = o1;
        }
    }
}

// ======================= copy observed rows into lstm_hidden ==================
__global__ void copy_obs_k(const float* __restrict__ obs, float* __restrict__ LH)
{
    size_t i = (size_t)blockIdx.x * blockDim.x + threadIdx.x;
    if (i < (size_t)Bn * OBSn * Hd) {
        size_t b = i >> 17;
        size_t rem = i & 131071;
        LH[b * 262144 + rem] = obs[i];
    }
}

// ============ persistent LSTM (v4: passing) ===================================
#define HSTRIDE 516
#define WSTRIDE 512
__global__ __launch_bounds__(256, 1) void lstm_persist(
    const float* __restrict__ obs, const float* __restrict__ XG,
    const float* __restrict__ Whh, float* __restrict__ LH)
{
    extern __shared__ float sh[];
    float* Hs = sh;
    float* Ws = sh + 64 * HSTRIDE;
    __shared__ float gsm[4 * 64 * 4];

    const int t = threadIdx.x;
    const int ublk = blockIdx.x * 4;
    const unsigned nb = gridDim.x;

    for (int idx = t; idx < 16 * 128; idx += 256) {
        int row = idx >> 7, qq = idx & 127;
        int g = row >> 2, j = row & 3;
        float4 v = *(const float4*)(Whh + (size_t)(g * 512 + ublk + j) * 512 + qq * 4);
        *(float4*)(Ws + row * WSTRIDE + qq * 4) = v;
    }

    const int wid = t >> 5, lane = t & 31;
    const int g = wid >> 1, bh = wid & 1;
    const int batch = bh * 32 + lane;

    const int pb = t >> 2, pj = t & 3;
    float c_reg = obs[(size_t)pb * 131072 + 255 * 512 + ublk + pj];

    const int crow = t >> 7;
    const int ccol = (t & 127) * 4;

    for (int s = 0; s < 256; s++) {
        const float* xrow = XG + (size_t)(pb * 256 + s) * 2048 + ublk + pj;
        float xg0 = __ldcg(xrow);
        float xg1 = __ldcg(xrow + 512);
        float xg2 = __ldcg(xrow + 1024);
        float xg3 = __ldcg(xrow + 1536);

        {
            const float* hsrc; size_t hstr;
            if (s == 0) { hsrc = obs + 255 * 512; hstr = 131072; }
            else        { hsrc = LH + (size_t)(255 + s) * 512; hstr = 262144; }
#pragma unroll
            for (int i = 0; i < 32; i++) {
                int r = 2 * i + crow;
                float4 v = __ldcg((const float4*)(hsrc + (size_t)r * hstr + ccol));
                *(float4*)(Hs + r * HSTRIDE + ccol) = v;
            }
        }
        __syncthreads();

        {
            const float* xp = Hs + batch * HSTRIDE;
            const float* wp = Ws + (g * 4) * WSTRIDE;
            float a0 = 0.f, a1 = 0.f, a2 = 0.f, a3 = 0.f;
#pragma unroll 8
            for (int k0 = 0; k0 < 512; k0 += 4) {
                float4 xv = *(const float4*)(xp + k0);
                float4 w0 = *(const float4*)(wp + k0);
                float4 w1 = *(const float4*)(wp + WSTRIDE + k0);
                float4 w2 = *(const float4*)(wp + 2 * WSTRIDE + k0);
                float4 w3 = *(const float4*)(wp + 3 * WSTRIDE + k0);
                a0 += xv.x * w0.x + xv.y * w0.y + xv.z * w0.z + xv.w * w0.w;
                a1 += xv.x * w1.x + xv.y * w1.y + xv.z * w1.z + xv.w * w1.w;
                a2 += xv.x * w2.x + xv.y * w2.y + xv.z * w2.z + xv.w * w2.w;
                a3 += xv.x * w3.x + xv.y * w3.y + xv.z * w3.z + xv.w * w3.w;
            }
            float4 o; o.x = a0; o.y = a1; o.z = a2; o.w = a3;
            *(float4*)(gsm + (g * 64 + batch) * 4) = o;
        }
        __syncthreads();

        {
            float gi = gsm[(0 * 64 + pb) * 4 + pj] + xg0;
            float gf = gsm[(1 * 64 + pb) * 4 + pj] + xg1;
            float gg = gsm[(2 * 64 + pb) * 4 + pj] + xg2;
            float go = gsm[(3 * 64 + pb) * 4 + pj] + xg3;
            c_reg = sigmoidf_(gf) * c_reg + sigmoidf_(gi) * tanhf(gg);
            float hv = sigmoidf_(go) * tanhf(c_reg);
            LH[(size_t)pb * 262144 + (size_t)(256 + s) * 512 + ublk + pj] = hv;
        }

        __threadfence();
        __syncthreads();
        if (t == 0) {
            unsigned snap = g_bar_gen;
            unsigned old = atomicAdd(&g_bar_cnt, 1u);
            if (old == nb - 1u) {
                g_bar_cnt = 0;
                __threadfence();
                g_bar_gen = snap + 1u;
            } else {
                while (g_bar_gen == snap) __nanosleep(32);
            }
            __threadfence();
        }
        __syncthreads();
    }
}

// ====================== fused GLU + LayerNorm =================================
__global__ __launch_bounds__(256) void gluln_k(
    const float* __restrict__ a1, const float* __restrict__ a2,
    const float* __restrict__ y1, const float* __restrict__ y2,
    const float* __restrict__ gamma, const float* __restrict__ beta,
    float* __restrict__ outp, int splitY)
{
    __shared__ float red[8];
    const int r = blockIdx.x;
    const int t = threadIdx.x;
    const float* yp;
    if (splitY) {
        int b = r >> 9, tt = r & 511;
        yp = (tt < 256) ? (y1 + ((size_t)(b * 256 + tt)) * 512)
                        : (y2 + ((size_t)(b * 256 + tt - 256)) * 512);
    } else {
        yp = y1 + (size_t)r * 512;
    }
    const float* p1 = a1 + (size_t)r * 512;
    const float* p2 = a2 + (size_t)r * 512;
    float z0 = sigmoidf_(p1[t])       * p2[t]       + yp[t];
    float z1 = sigmoidf_(p1[t + 256]) * p2[t + 256] + yp[t + 256];

    float s = z0 + z1;
#pragma unroll
    for (int o = 16; o > 0; o >>= 1) s += __shfl_xor_sync(0xffffffffu, s, o);
    if ((t & 31) == 0) red[t >> 5] = s;
    __syncthreads();
    if (t < 32) {
        float a = (t < 8) ? red[t] : 0.0f;
#pragma unroll
        for (int o = 4; o > 0; o >>= 1) a += __shfl_xor_sync(0xffffffffu, a, o);
        if (t == 0) red[0] = a;
    }
    __syncthreads();
    float mu = red[0] * (1.0f / 512.0f);
    float d0 = z0 - mu, d1 = z1 - mu;
    float s2 = d0 * d0 + d1 * d1;
    __syncthreads();
#pragma unroll
    for (int o = 16; o > 0; o >>= 1) s2 += __shfl_xor_sync(0xffffffffu, s2, o);
    if ((t & 31) == 0) red[t >> 5] = s2;
    __syncthreads();
    if (t < 32) {
        float a = (t < 8) ? red[t] : 0.0f;
#pragma unroll
        for (int o = 4; o > 0; o >>= 1) a += __shfl_xor_sync(0xffffffffu, a, o);
        if (t == 0) red[0] = a;
    }
    __syncthreads();
    float inv = rsqrtf(red[0] * (1.0f / 512.0f) + 1e-5f);
    outp[(size_t)r * 512 + t]       = gamma[t]       * d0 * inv + beta[t];
    outp[(size_t)r * 512 + t + 256] = gamma[t + 256] * d1 * inv + beta[t + 256];
}

// ========================= row softmax over 512 cols ==========================
__global__ __launch_bounds__(256) void softmax_k(
    const float* __restrict__ S, float* __restrict__ A)
{
    __shared__ float red[8];
    const int r = blockIdx.x;
    const int t = threadIdx.x;
    const float* p = S + (size_t)r * 512;
    float v0 = p[t], v1 = p[t + 256];
    float m = fmaxf(v0, v1);
#pragma unroll
    for (int o = 16; o > 0; o >>= 1) m = fmaxf(m, __shfl_xor_sync(0xffffffffu, m, o));
    if ((t & 31) == 0) red[t >> 5] = m;
    __syncthreads();
    if (t < 32) {
        float a = (t < 8) ? red[t] : -3.4e38f;
#pragma unroll
        for (int o = 4; o > 0; o >>= 1) a = fmaxf(a, __shfl_xor_sync(0xffffffffu, a, o));
        if (t == 0) red[0] = a;
    }
    __syncthreads();
    float mx = red[0];
    float e0 = expf(v0 - mx), e1 = expf(v1 - mx);
    float s = e0 + e1;
    __syncthreads();
#pragma unroll
    for (int o = 16; o > 0; o >>= 1) s += __shfl_xor_sync(0xffffffffu, s, o);
    if ((t & 31) == 0) red[t >> 5] = s;
    __syncthreads();
    if (t < 32) {
        float a = (t < 8) ? red[t] : 0.0f;
#pragma unroll
        for (int o = 4; o > 0; o >>= 1) a += __shfl_xor_sync(0xffffffffu, a, o);
        if (t == 0) red[0] = a;
    }
    __syncthreads();
    float inv = 1.0f / red[0];
    A[(size_t)r * 512 + t]       = e0 * inv;
    A[(size_t)r * 512 + t + 256] = e1 * inv;
}

// ================================= host =======================================
extern "C" void kernel_launch(void* const* d_in, const int* in_sizes, int n_in,
                              void* d_out, int out_size)
{
    const float* obs   = (const float*)d_in[0];
    const float* fut   = (const float*)d_in[1];
    const float* W_ih  = (const float*)d_in[2];
    const float* W_hh  = (const float*)d_in[3];
    const float* b_ih  = (const float*)d_in[4];
    const float* b_hh  = (const float*)d_in[5];
    const float* g1W1  = (const float*)d_in[6];
    const float* g1b1  = (const float*)d_in[7];
    const float* g1W2  = (const float*)d_in[8];
    const float* g1b2  = (const float*)d_in[9];
    const float* g1g   = (const float*)d_in[10];
    const float* g1b   = (const float*)d_in[11];
    const float* Wq    = (const float*)d_in[12];
    const float* bq    = (const float*)d_in[13];
    const float* Wk    = (const float*)d_in[14];
    const float* bk    = (const float*)d_in[15];
    const float* Wv    = (const float*)d_in[16];
    const float* bv    = (const float*)d_in[17];
    const float* Wo    = (const float*)d_in[18];
    const float* bo    = (const float*)d_in[19];
    const float* g2W1  = (const float*)d_in[20];
    const float* g2b1  = (const float*)d_in[21];
    const float* g2W2  = (const float*)d_in[22];
    const float* g2b2  = (const float*)d_in[23];
    const float* g2g   = (const float*)d_in[24];
    const float* g2b   = (const float*)d_in[25];

    float* out       = (float*)d_out;
    float* glu_delta = out;
    float* glu_phi   = out + (size_t)OUT1;
    float* attn      = out + (size_t)2 * OUT1;

    float *XG, *LH, *A1, *A2, *Qb, *Kb, *Vb;
    cudaGetSymbolAddress((void**)&XG, d_XG);
    cudaGetSymbolAddress((void**)&LH, d_LH);
    cudaGetSymbolAddress((void**)&A1, d_A1);
    cudaGetSymbolAddress((void**)&A2, d_A2);
    cudaGetSymbolAddress((void**)&Qb, d_Qb);
    cudaGetSymbolAddress((void**)&Kb, d_Kb);
    cudaGetSymbolAddress((void**)&Vb, d_Vb);

    // 1. X_gates = fut @ W_ih^T + (b_ih + b_hh)
    gemm_mma<<<dim3(G4 / 128, BF / 128), 256>>>(fut, W_ih, b_ih, b_hh, XG, BF, G4, Hd);

    // 2. lstm_hidden[:, :256, :] = vsn_observed
    copy_obs_k<<<(Bn * OBSn * Hd + 255) / 256, 256>>>(obs, LH);

    // 3. persistent LSTM over all 256 steps
    {
        const int smem = (64 * HSTRIDE + 16 * WSTRIDE) * 4;
        cudaFuncSetAttribute(lstm_persist, cudaFuncAttributeMaxDynamicSharedMemorySize, smem);
        lstm_persist<<<128, 256, smem>>>(obs, XG, W_hh, LH);
    }

    // 4. GLU-LN #1 -> glu_phi
    gemm_mma<<<dim3(4, 256), 256>>>(LH, g1W1, g1b1, nullptr, A1, BT, Hd, Hd);
    gemm_mma<<<dim3(4, 256), 256>>>(LH, g1W2, g1b2, nullptr, A2, BT, Hd, Hd);
    gluln_k<<<BT, 256>>>(A1, A2, obs, fut, g1g, g1b, glu_phi, 1);

    // 5. QKV
    gemm_mma<<<dim3(4, 256), 256>>>(glu_phi, Wq, bq, nullptr, Qb, BT, Hd, Hd);
    gemm_mma<<<dim3(4, 256), 256>>>(glu_phi, Wk, bk, nullptr, Kb, BT, Hd, Hd);
    gemm_mma<<<dim3(4, 256), 256>>>(glu_phi, Wv, bv, nullptr, Vb, BT, Hd, Hd);

    // 6. scores (reuse XG) + softmax -> attn
    gemm_mma_scores<<<dim3(4, 4, 64), 256>>>(Qb, Kb, XG, 0.04419417382415922f);
    softmax_k<<<BT, 256>>>(XG, attn);

    // 7. attn @ V -> reuse Qb; projection -> reuse Kb
    gemm_mma_av<<<dim3(4, 4, 64), 256>>>(attn, Vb, Qb);
    gemm_mma<<<dim3(4, 256), 256>>>(Qb, Wo, bo, nullptr, Kb, BT, Hd, Hd);

    // 8. GLU-LN #2 -> glu_delta
    gemm_mma<<<dim3(4, 256), 256>>>(Kb, g2W1, g2b1, nullptr, A1, BT, Hd, Hd);
    gemm_mma<<<dim3(4, 256), 256>>>(Kb, g2W2, g2b2, nullptr, A2, BT, Hd, Hd);
    gluln_k<<<BT, 256>>>(A1, A2, glu_phi, nullptr, g2g, g2b, glu_delta, 0);
}